// round 2
// baseline (speedup 1.0000x reference)
#include <cuda_runtime.h>

// ---------------------------------------------------------------------------
// PivNet fused kernel — round 2: fp32x2 packed-FFMA, fully smem-resident,
// persistent, no gmem scratch.
//
// Per 64-row tile:
//   stage0 : grid-hash -> idx, gather pivot+knnd, build feat[64][108] in smem
//   layer1 : feat(105) @ W1 -> relu -> sH (smem, regs->smem, no hazard)
//   layer2 : sH @ W2 -> regs -> sync -> relu-store in place -> sync
//   layer3 : same
//   layer4 : sH @ W4(512x100) + b4 -> out (gmem, coalesced)
// All FMAs are fma.rn.f32x2 (FFMA2): exact fp32, 2x throughput.
// ---------------------------------------------------------------------------

#define B_TOTAL   524288
#define DIMN      4
#define GRIDN     16
#define KN        100
#define HN        512
#define FEATN     105

#define TM        64
#define THREADS   512
#define NTILES    (B_TOTAL / TM)     // 8192
#define GRID_CTAS 152

#define PITCH_H   516
#define PITCH_F   108

#define SM_H      (TM * PITCH_H)
#define SM_F      (TM * PITCH_F)
#define SM_TOTALF (SM_H + SM_F + KN + KN + TM)
#define SMEM_BYTES (SM_TOTALF * 4)   // 160,800 B

typedef unsigned long long ull;

__device__ __forceinline__ ull pk2(float lo, float hi) {
    ull r; asm("mov.b64 %0, {%1,%2};" : "=l"(r) : "f"(lo), "f"(hi)); return r;
}
__device__ __forceinline__ void fma2(ull& d, ull a, ull b) {
    asm("fma.rn.f32x2 %0, %1, %2, %3;" : "=l"(d) : "l"(a), "l"(b), "l"(d));
}
__device__ __forceinline__ float2 upk(ull v) {
    float2 r; asm("mov.b64 {%0,%1}, %2;" : "=f"(r.x), "=f"(r.y) : "l"(v)); return r;
}

// ---------------------------------------------------------------------------
// Layers 1-3 compute: 8 rows x 8 cols per thread, acc in regs.
//   rowg = tid>>6 (8 groups of 8 rows), colg = tid&63 (8 cols each, 512 total)
// a-loads are warp-wide smem broadcasts; W streamed from gmem (L1 broadcast).
// ---------------------------------------------------------------------------
template<int Kd, int PITCH>
__device__ __forceinline__ void gemm_compute(
    const float* __restrict__ sIn,
    const float* __restrict__ W,
    ull acc[8][4], int r0, int c0)
{
    #pragma unroll
    for (int i = 0; i < 8; i++)
        #pragma unroll
        for (int jp = 0; jp < 4; jp++) acc[i][jp] = 0ULL;

    const float* wk = W + c0;
    const float* ak = sIn + r0 * PITCH;
    #pragma unroll 2
    for (int k = 0; k < Kd; k++) {
        const float4 wA = *reinterpret_cast<const float4*>(wk);
        const float4 wB = *reinterpret_cast<const float4*>(wk + 4);
        wk += HN;
        const ull w0 = pk2(wA.x, wA.y);
        const ull w1 = pk2(wA.z, wA.w);
        const ull w2 = pk2(wB.x, wB.y);
        const ull w3 = pk2(wB.z, wB.w);
        #pragma unroll
        for (int i = 0; i < 8; i++) {
            const float a = ak[i * PITCH + k];
            const ull aa = pk2(a, a);
            fma2(acc[i][0], aa, w0);
            fma2(acc[i][1], aa, w1);
            fma2(acc[i][2], aa, w2);
            fma2(acc[i][3], aa, w3);
        }
    }
}

// Store acc (+bias, relu) into sH[r0..r0+7][c0..c0+7].
__device__ __forceinline__ void store_relu(
    ull acc[8][4], float* __restrict__ sH,
    const float* __restrict__ bias, int r0, int c0)
{
    const float4 bA = *reinterpret_cast<const float4*>(bias + c0);
    const float4 bB = *reinterpret_cast<const float4*>(bias + c0 + 4);
    #pragma unroll
    for (int i = 0; i < 8; i++) {
        const float2 v0 = upk(acc[i][0]);
        const float2 v1 = upk(acc[i][1]);
        const float2 v2 = upk(acc[i][2]);
        const float2 v3 = upk(acc[i][3]);
        float* dst = sH + (r0 + i) * PITCH_H + c0;
        *reinterpret_cast<float4*>(dst) = make_float4(
            fmaxf(v0.x + bA.x, 0.f), fmaxf(v0.y + bA.y, 0.f),
            fmaxf(v1.x + bA.z, 0.f), fmaxf(v1.y + bA.w, 0.f));
        *reinterpret_cast<float4*>(dst + 4) = make_float4(
            fmaxf(v2.x + bB.x, 0.f), fmaxf(v2.y + bB.y, 0.f),
            fmaxf(v3.x + bB.z, 0.f), fmaxf(v3.y + bB.w, 0.f));
    }
}

extern "C" __global__ void __launch_bounds__(THREADS, 1)
pivnet_fused(
    const float* __restrict__ x,
    const float* __restrict__ minv,  const float* __restrict__ maxv,
    const float* __restrict__ pivots, const float* __restrict__ knnd,
    const float* __restrict__ qmean, const float* __restrict__ qstd,
    const float* __restrict__ kmean, const float* __restrict__ kstd,
    const float* __restrict__ W1, const float* __restrict__ b1,
    const float* __restrict__ W2, const float* __restrict__ b2,
    const float* __restrict__ W3, const float* __restrict__ b3,
    const float* __restrict__ W4, const float* __restrict__ b4,
    float* __restrict__ out)
{
    extern __shared__ float smem[];
    float* sH   = smem;                 // [TM][PITCH_H]
    float* sF   = sH + SM_H;            // [TM][PITCH_F]
    float* sKm  = sF + SM_F;            // [KN]
    float* sKi  = sKm + KN;             // [KN]
    int*   sIdx = (int*)(sKi + KN);     // [TM]

    const int tid  = threadIdx.x;
    const int rowg = tid >> 6;          // 0..7
    const int colg = tid & 63;          // 0..63
    const int r0   = rowg * 8;
    const int c0   = colg * 8;

    for (int j = tid; j < KN; j += THREADS) {
        sKm[j] = kmean[j];
        sKi[j] = 1.f / kstd[j];
    }
    __syncthreads();

    for (int tile = blockIdx.x; tile < NTILES; tile += GRID_CTAS) {
        const int rowbase = tile * TM;

        // ---- stage 0a: per-row idx, qn, dist (threads 0..63) ----
        if (tid < TM) {
            const int row = rowbase + tid;
            float xv[DIMN];
            int idx = 0;
            float diag2 = 0.f;
            #pragma unroll
            for (int d = 0; d < DIMN; d++) {
                xv[d] = x[row * DIMN + d];
                const float mn = minv[d], mx = maxv[d];
                const float s = (xv[d] - mn) / (mx - mn) * (float)GRIDN;
                int bi = (int)floorf(s);
                bi = bi < 0 ? 0 : (bi > GRIDN - 1 ? GRIDN - 1 : bi);
                idx = idx * GRIDN + bi;
                const float bw = (mx - mn) * (1.f / GRIDN);
                diag2 += bw * bw;
                sF[tid * PITCH_F + d] = (xv[d] - qmean[d]) / qstd[d];
            }
            sIdx[tid] = idx;
            float d2 = 0.f;
            #pragma unroll
            for (int d = 0; d < DIMN; d++) {
                const float dd = xv[d] - pivots[idx * DIMN + d];
                d2 += dd * dd;
            }
            sF[tid * PITCH_F + DIMN] = sqrtf(d2 / diag2);
            // zero-pad feat cols 105..107 (PITCH_F covers 108)
            sF[tid * PITCH_F + 105] = 0.f;
            sF[tid * PITCH_F + 106] = 0.f;
            sF[tid * PITCH_F + 107] = 0.f;
        }
        __syncthreads();

        // ---- stage 0b: gather + normalize knnd (coalesced per row) ----
        for (int i = tid; i < TM * KN; i += THREADS) {
            const int r = i / KN;
            const int j = i - r * KN;
            const float v = knnd[(size_t)sIdx[r] * KN + j];
            sF[r * PITCH_F + DIMN + 1 + j] = (v - sKm[j]) * sKi[j];
        }
        __syncthreads();

        ull acc[8][4];

        // ---- layer 1: feat(105) -> 512, relu (reads sF, writes sH) ----
        gemm_compute<FEATN, PITCH_F>(sF, W1, acc, r0, c0);
        store_relu(acc, sH, b1, r0, c0);
        __syncthreads();

        // ---- layer 2: in place on sH ----
        gemm_compute<HN, PITCH_H>(sH, W2, acc, r0, c0);
        __syncthreads();
        store_relu(acc, sH, b2, r0, c0);
        __syncthreads();

        // ---- layer 3 ----
        gemm_compute<HN, PITCH_H>(sH, W3, acc, r0, c0);
        __syncthreads();
        store_relu(acc, sH, b3, r0, c0);
        __syncthreads();

        // ---- layer 4: 512 -> 100, no relu, straight to out ----
        // mapping: 16 row-groups x 4 rows, 32 col-groups x 4 cols (25 active)
        {
            const int rg4 = tid >> 5;        // 0..15
            const int cg4 = tid & 31;        // 0..31
            const int rr0 = rg4 * 4;
            const int cc0 = cg4 * 4;
            if (cc0 < KN) {                  // 100 % 4 == 0: no partials
                ull a4[4][2];
                #pragma unroll
                for (int i = 0; i < 4; i++) { a4[i][0] = 0ULL; a4[i][1] = 0ULL; }
                const float* wk = W4 + cc0;
                const float* ak = sH + rr0 * PITCH_H;
                #pragma unroll 2
                for (int k = 0; k < HN; k++) {
                    const float4 wA = *reinterpret_cast<const float4*>(wk);
                    wk += KN;
                    const ull w0 = pk2(wA.x, wA.y);
                    const ull w1 = pk2(wA.z, wA.w);
                    #pragma unroll
                    for (int i = 0; i < 4; i++) {
                        const float a = ak[i * PITCH_H + k];
                        const ull aa = pk2(a, a);
                        fma2(a4[i][0], aa, w0);
                        fma2(a4[i][1], aa, w1);
                    }
                }
                const float4 bb = *reinterpret_cast<const float4*>(b4 + cc0);
                float* og = out + (size_t)(rowbase + rr0) * KN + cc0;
                #pragma unroll
                for (int i = 0; i < 4; i++) {
                    const float2 v0 = upk(a4[i][0]);
                    const float2 v1 = upk(a4[i][1]);
                    *reinterpret_cast<float4*>(og + (size_t)i * KN) = make_float4(
                        v0.x + bb.x, v0.y + bb.y, v1.x + bb.z, v1.y + bb.w);
                }
            }
        }
        __syncthreads();   // protect sH before next tile's layer 1 write
    }
}

extern "C" void kernel_launch(void* const* d_in, const int* in_sizes, int n_in,
                              void* d_out, int out_size)
{
    const float* x     = (const float*)d_in[0];
    const float* minv  = (const float*)d_in[1];
    const float* maxv  = (const float*)d_in[2];
    const float* piv   = (const float*)d_in[3];
    const float* knnd  = (const float*)d_in[4];
    const float* qmean = (const float*)d_in[5];
    const float* qstd  = (const float*)d_in[6];
    const float* kmean = (const float*)d_in[7];
    const float* kstd  = (const float*)d_in[8];
    const float* W1    = (const float*)d_in[9];
    const float* b1    = (const float*)d_in[10];
    const float* W2    = (const float*)d_in[11];
    const float* b2    = (const float*)d_in[12];
    const float* W3    = (const float*)d_in[13];
    const float* b3    = (const float*)d_in[14];
    const float* W4    = (const float*)d_in[15];
    const float* b4    = (const float*)d_in[16];
    float* out = (float*)d_out;

    cudaFuncSetAttribute(pivnet_fused,
                         cudaFuncAttributeMaxDynamicSharedMemorySize, SMEM_BYTES);

    pivnet_fused<<<GRID_CTAS, THREADS, SMEM_BYTES>>>(
        x, minv, maxv, piv, knnd, qmean, qstd, kmean, kstd,
        W1, b1, W2, b2, W3, b3, W4, b4, out);
}

// round 5
// speedup vs baseline: 8.1087x; 8.1087x over previous
#include <cuda_runtime.h>
#include <cuda_fp16.h>
#include <cstdint>
#include <cstring>

// ===========================================================================
// PivNet — mma.sync (HMMA) tensor-core version. fp16 in, fp32 accumulate.
//   NOTE: tcgen05 is unavailable (harness compiles PTX for compute_103, not
//   compute_103a) — mma.sync m16n8k16 is baseline PTX and hits the tensor pipe.
//   prepack : W* -> fp16 B-fragment images (exact per-lane mma layout, gmem)
//   main    : persistent, 64-row tiles, A in ping-pong smem via ldmatrix
// ===========================================================================

#define B_TOTAL   524288
#define DIMN      4
#define KN        100
#define TILE_M    64
#define THREADS   512
#define NTILES    (B_TOTAL / TILE_M)   // 8192
#define GRID_CTAS 152
#define PITCH     520                  // halfs; 1040B row stride, ldmatrix-conflict-free

// fragment image offsets (uint4 units)
#define OFF1 0                          // W1: K=112(pad) x N=512 -> 7168
#define OFF2 7168                       // W2: 512x512 -> 32768
#define OFF3 39936                      // W3: 512x512
#define OFF4 72704                      // W4: K=512 x N=128(pad) -> 8192
#define IMG_U4 80896                    // total ~1.26 MB

__device__ __align__(16) uint4 g_Wfrag[IMG_U4];

// smem layout (bytes)
#define SM_BUF_BYTES (TILE_M * PITCH * 2)   // 66560
#define SM_A0   0
#define SM_A1   SM_BUF_BYTES
#define SM_KM   (2 * SM_BUF_BYTES)          // 133120: 100 floats
#define SM_KI   (SM_KM + 400)
#define SM_IDX  (SM_KI + 400)               // 64 ints
#define SMEM_BYTES (SM_IDX + 256 + 32)

// ---------------------------------------------------------------------------
__device__ __forceinline__ uint32_t smem_u32(const void* p) {
    uint32_t a;
    asm("{ .reg .u64 t; cvta.to.shared.u64 t, %1; cvt.u32.u64 %0, t; }"
        : "=r"(a) : "l"(p));
    return a;
}
__device__ __forceinline__ void ldmA(uint32_t a[4], uint32_t addr) {
    asm volatile("ldmatrix.sync.aligned.m8n8.x4.shared.b16 {%0,%1,%2,%3}, [%4];"
                 : "=r"(a[0]), "=r"(a[1]), "=r"(a[2]), "=r"(a[3]) : "r"(addr));
}
__device__ __forceinline__ void mma16816(float c[4], const uint32_t a[4],
                                         uint32_t b0, uint32_t b1) {
    asm volatile("mma.sync.aligned.m16n8k16.row.col.f32.f16.f16.f32 "
                 "{%0,%1,%2,%3}, {%4,%5,%6,%7}, {%8,%9}, {%0,%1,%2,%3};"
                 : "+f"(c[0]), "+f"(c[1]), "+f"(c[2]), "+f"(c[3])
                 : "r"(a[0]), "r"(a[1]), "r"(a[2]), "r"(a[3]), "r"(b0), "r"(b1));
}
__device__ __forceinline__ uint32_t packh2(float lo, float hi) {
    __half2 h = __floats2half2_rn(lo, hi);
    uint32_t u; memcpy(&u, &h, 4); return u;
}

// ---------------------------------------------------------------------------
// prepack: W (fp32 [K][N] row-major) -> per-lane mma B fragment uint4 image.
// uint4 index u: kblk = u/PB, npair = (u%PB)>>5, lane = u&31 (PB=(N/16)*32)
//   g = lane>>2 (n within 8-block), tig = lane&3 (k pair)
//   x = {W[k0+2tig][na], W[k0+2tig+1][na]}   y = {.. +8 ..}   (na = npair*16+g)
//   z,w = same at nb = na+8
// ---------------------------------------------------------------------------
extern "C" __global__ void pivnet_prepack(
    const float* __restrict__ W1, const float* __restrict__ W2,
    const float* __restrict__ W3, const float* __restrict__ W4)
{
    for (int u = blockIdx.x * blockDim.x + threadIdx.x; u < IMG_U4;
         u += gridDim.x * blockDim.x) {
        const float* W; int Ksrc, Nsrc, stride, npairs, lu;
        if (u < OFF2)      { W = W1; Ksrc = 105; Nsrc = 512; stride = 512; npairs = 32; lu = u - OFF1; }
        else if (u < OFF3) { W = W2; Ksrc = 512; Nsrc = 512; stride = 512; npairs = 32; lu = u - OFF2; }
        else if (u < OFF4) { W = W3; Ksrc = 512; Nsrc = 512; stride = 512; npairs = 32; lu = u - OFF3; }
        else               { W = W4; Ksrc = 512; Nsrc = 100; stride = 100; npairs = 8;  lu = u - OFF4; }
        const int PB = npairs * 32;
        const int kblk = lu / PB, rem = lu - kblk * PB;
        const int npair = rem >> 5, lane = rem & 31;
        const int g = lane >> 2, tig = lane & 3;
        const int k0 = kblk * 16 + tig * 2;
        const int na = npair * 16 + g, nb = na + 8;
        auto rd = [&](int k, int n) -> float {
            return (k < Ksrc && n < Nsrc) ? W[k * stride + n] : 0.f;
        };
        uint4 v;
        v.x = packh2(rd(k0,     na), rd(k0 + 1, na));
        v.y = packh2(rd(k0 + 8, na), rd(k0 + 9, na));
        v.z = packh2(rd(k0,     nb), rd(k0 + 1, nb));
        v.w = packh2(rd(k0 + 8, nb), rd(k0 + 9, nb));
        g_Wfrag[u] = v;
    }
}

// ---------------------------------------------------------------------------
// one 64-col pass: 8 n-frags, KSTEPS k-steps. imgp pre-offset to npair0, lane.
// ---------------------------------------------------------------------------
template<int KSTEPS>
__device__ __forceinline__ void mma_pass(
    uint32_t aAddr, const uint4* __restrict__ imgp, int kstride_u4,
    float acc[8][4])
{
    #pragma unroll
    for (int i = 0; i < 8; i++)
        acc[i][0] = acc[i][1] = acc[i][2] = acc[i][3] = 0.f;
    #pragma unroll 4
    for (int ks = 0; ks < KSTEPS; ks++) {
        uint32_t a[4];
        ldmA(a, aAddr); aAddr += 32;
        #pragma unroll
        for (int p = 0; p < 4; p++) {
            const uint4 v = __ldg(imgp + p * 32);
            mma16816(acc[2 * p],     a, v.x, v.y);
            mma16816(acc[2 * p + 1], a, v.z, v.w);
        }
        imgp += kstride_u4;
    }
}

__device__ __forceinline__ void epi_relu(
    const float acc[8][4], char* __restrict__ dst, const float* __restrict__ bias,
    int m0, int g, int tig, int cbase)
{
    #pragma unroll
    for (int f = 0; f < 8; f++) {
        const int c = cbase + f * 8 + tig * 2;
        const float b0 = __ldg(bias + c), b1 = __ldg(bias + c + 1);
        __half2 lo = __floats2half2_rn(fmaxf(acc[f][0] + b0, 0.f),
                                       fmaxf(acc[f][1] + b1, 0.f));
        __half2 hi = __floats2half2_rn(fmaxf(acc[f][2] + b0, 0.f),
                                       fmaxf(acc[f][3] + b1, 0.f));
        *(__half2*)(dst + ((m0 + g)     * PITCH + c) * 2) = lo;
        *(__half2*)(dst + ((m0 + g + 8) * PITCH + c) * 2) = hi;
    }
}

// relu layer: src(smem,u32 base) -> dst(smem), warp covers 16 rows x 128 cols
template<int KSTEPS>
__device__ __forceinline__ void layer_relu(
    uint32_t srcU32, char* __restrict__ dst, const uint4* __restrict__ img,
    const float* __restrict__ bias,
    int m0, int colg, int lane, int g, int tig)
{
    const int row  = m0 + (lane & 7) + ((lane >> 3) & 1) * 8;
    const int colb = (lane >> 4) * 8;
    const uint32_t aAddr = srcU32 + (row * PITCH + colb) * 2;
    float acc[8][4];
    #pragma unroll
    for (int h = 0; h < 2; h++) {
        const int npair0 = colg * 8 + h * 4;
        mma_pass<KSTEPS>(aAddr, img + npair0 * 32 + lane, 32 * 32, acc);
        epi_relu(acc, dst, bias, m0, g, tig, colg * 128 + h * 64);
    }
}

// output layer: N=128(pad), warp covers 16 rows x 32 cols, store n<100
__device__ __forceinline__ void layer_out(
    uint32_t srcU32, const uint4* __restrict__ img,
    const float* __restrict__ b4, float* __restrict__ outg,
    int m0, int colg, int lane, int g, int tig)
{
    const int row  = m0 + (lane & 7) + ((lane >> 3) & 1) * 8;
    const int colb = (lane >> 4) * 8;
    uint32_t aAddr = srcU32 + (row * PITCH + colb) * 2;
    float acc[4][4];
    #pragma unroll
    for (int i = 0; i < 4; i++)
        acc[i][0] = acc[i][1] = acc[i][2] = acc[i][3] = 0.f;
    const uint4* imgp = img + (colg * 2) * 32 + lane;
    #pragma unroll 4
    for (int ks = 0; ks < 32; ks++) {
        uint32_t a[4];
        ldmA(a, aAddr); aAddr += 32;
        const uint4 v0 = __ldg(imgp);
        const uint4 v1 = __ldg(imgp + 32);
        mma16816(acc[0], a, v0.x, v0.y);
        mma16816(acc[1], a, v0.z, v0.w);
        mma16816(acc[2], a, v1.x, v1.y);
        mma16816(acc[3], a, v1.z, v1.w);
        imgp += 8 * 32;
    }
    #pragma unroll
    for (int f = 0; f < 4; f++) {
        const int n = colg * 32 + f * 8 + tig * 2;
        if (n < KN) {
            const float b0 = __ldg(b4 + n), b1 = __ldg(b4 + n + 1);
            *(float2*)(outg + (m0 + g)     * KN + n) =
                make_float2(acc[f][0] + b0, acc[f][1] + b1);
            *(float2*)(outg + (m0 + g + 8) * KN + n) =
                make_float2(acc[f][2] + b0, acc[f][3] + b1);
        }
    }
}

// ---------------------------------------------------------------------------
extern "C" __global__ void __launch_bounds__(THREADS, 1)
pivnet_mma(
    const float* __restrict__ x,
    const float* __restrict__ minv,  const float* __restrict__ maxv,
    const float* __restrict__ pivots, const float* __restrict__ knnd,
    const float* __restrict__ qmean, const float* __restrict__ qstd,
    const float* __restrict__ kmean, const float* __restrict__ kstd,
    const float* __restrict__ b1, const float* __restrict__ b2,
    const float* __restrict__ b3, const float* __restrict__ b4,
    float* __restrict__ out)
{
    extern __shared__ char smem[];
    char*  sA0  = smem + SM_A0;
    char*  sA1  = smem + SM_A1;
    float* sKm  = (float*)(smem + SM_KM);
    float* sKi  = (float*)(smem + SM_KI);
    int*   sIdx = (int*)(smem + SM_IDX);

    const int tid  = threadIdx.x;
    const int wid  = tid >> 5;
    const int lane = tid & 31;
    const int g    = lane >> 2;
    const int tig  = lane & 3;
    const int rowg = wid & 3;          // 4 row groups of 16
    const int colg = wid >> 2;         // 4 col groups of 128
    const int m0   = rowg * 16;

    const uint32_t a0u = smem_u32(sA0);
    const uint32_t a1u = smem_u32(sA1);

    for (int j = tid; j < KN; j += THREADS) {
        sKm[j] = kmean[j];
        sKi[j] = 1.f / kstd[j];
    }
    __syncthreads();

    for (int tile = blockIdx.x; tile < NTILES; tile += gridDim.x) {
        const int rowbase = tile * TILE_M;

        // ---- stage 0a: idx, qn, dist, zero-pad (threads 0..63) ----
        if (tid < TILE_M) {
            const int row = rowbase + tid;
            const float4 xv4 = __ldg((const float4*)x + row);
            float xs[4] = {xv4.x, xv4.y, xv4.z, xv4.w};
            int idx = 0;
            float diag2 = 0.f;
            __half* arow = (__half*)(sA0 + tid * PITCH * 2);
            #pragma unroll
            for (int d = 0; d < DIMN; d++) {
                const float mn = minv[d], mx = maxv[d];
                const float s = (xs[d] - mn) / (mx - mn) * 16.f;
                int bi = (int)floorf(s);
                bi = bi < 0 ? 0 : (bi > 15 ? 15 : bi);
                idx = (idx << 4) + bi;
                const float bw = (mx - mn) * 0.0625f;
                diag2 += bw * bw;
                arow[d] = __float2half((xs[d] - qmean[d]) / qstd[d]);
            }
            sIdx[tid] = idx;
            float d2 = 0.f;
            #pragma unroll
            for (int d = 0; d < DIMN; d++) {
                const float dd = xs[d] - pivots[idx * DIMN + d];
                d2 += dd * dd;
            }
            arow[DIMN] = __float2half(sqrtf(d2 / diag2));
            #pragma unroll
            for (int c = 105; c < 112; c++) arow[c] = __half(0.f);
        }
        __syncthreads();

        // ---- stage 0b: knnd gather (coalesced within rows) ----
        for (int i = tid; i < TILE_M * KN; i += THREADS) {
            const int r = i / KN, j = i - r * KN;
            const float v = __ldg(knnd + (size_t)sIdx[r] * KN + j);
            ((__half*)(sA0 + r * PITCH * 2))[DIMN + 1 + j] =
                __float2half((v - sKm[j]) * sKi[j]);
        }
        __syncthreads();

        // ---- layers ----
        layer_relu<7> (a0u, sA1, g_Wfrag + OFF1, b1, m0, colg, lane, g, tig);
        __syncthreads();
        layer_relu<32>(a1u, sA0, g_Wfrag + OFF2, b2, m0, colg, lane, g, tig);
        __syncthreads();
        layer_relu<32>(a0u, sA1, g_Wfrag + OFF3, b3, m0, colg, lane, g, tig);
        __syncthreads();
        layer_out(a1u, g_Wfrag + OFF4, b4, out + (size_t)rowbase * KN,
                  m0, colg, lane, g, tig);
        __syncthreads();
    }
}

// ---------------------------------------------------------------------------
extern "C" void kernel_launch(void* const* d_in, const int* in_sizes, int n_in,
                              void* d_out, int out_size)
{
    const float* x     = (const float*)d_in[0];
    const float* minv  = (const float*)d_in[1];
    const float* maxv  = (const float*)d_in[2];
    const float* piv   = (const float*)d_in[3];
    const float* knnd  = (const float*)d_in[4];
    const float* qmean = (const float*)d_in[5];
    const float* qstd  = (const float*)d_in[6];
    const float* kmean = (const float*)d_in[7];
    const float* kstd  = (const float*)d_in[8];
    const float* W1    = (const float*)d_in[9];
    const float* b1    = (const float*)d_in[10];
    const float* W2    = (const float*)d_in[11];
    const float* b2    = (const float*)d_in[12];
    const float* W3    = (const float*)d_in[13];
    const float* b3    = (const float*)d_in[14];
    const float* W4    = (const float*)d_in[15];
    const float* b4    = (const float*)d_in[16];
    float* out = (float*)d_out;

    pivnet_prepack<<<256, 256>>>(W1, W2, W3, W4);

    cudaFuncSetAttribute(pivnet_mma,
                         cudaFuncAttributeMaxDynamicSharedMemorySize, SMEM_BYTES);
    pivnet_mma<<<GRID_CTAS, THREADS, SMEM_BYTES>>>(
        x, minv, maxv, piv, knnd, qmean, qstd, kmean, kstd,
        b1, b2, b3, b4, out);
}

// round 7
// speedup vs baseline: 8.4097x; 1.0371x over previous
#include <cuda_runtime.h>
#include <cuda_fp16.h>
#include <cstdint>
#include <cstring>

// ===========================================================================
// PivNet — mma.sync (HMMA), fp16 in / fp32 acc.
// Round 6: warp map 2 rowg x 8 colg (32 rows x 64 cols per warp) halves the
// W-fragment LDG duplication (4x -> 2x), flipping L1tex-bound -> tensor-bound.
// ===========================================================================

#define B_TOTAL   524288
#define DIMN      4
#define KN        100
#define TILE_M    64
#define THREADS   512
#define NTILES    (B_TOTAL / TILE_M)   // 8192
#define GRID_CTAS 152
#define PITCH     520                  // halfs

// fragment image offsets (uint4 units)
#define OFF1 0                          // W1: K=112(pad) x N=512
#define OFF2 7168
#define OFF3 39936
#define OFF4 72704                      // W4: K=512 x N=128(pad)
#define IMG_U4 80896

__device__ __align__(16) uint4 g_Wfrag[IMG_U4];

// smem layout (bytes)
#define SM_BUF_BYTES (TILE_M * PITCH * 2)   // 66560
#define SM_A0   0
#define SM_A1   SM_BUF_BYTES
#define SM_KM   (2 * SM_BUF_BYTES)
#define SM_KI   (SM_KM + 400)
#define SM_IDX  (SM_KI + 400)
#define SMEM_BYTES (SM_IDX + 256 + 32)

// ---------------------------------------------------------------------------
__device__ __forceinline__ uint32_t smem_u32(const void* p) {
    uint32_t a;
    asm("{ .reg .u64 t; cvta.to.shared.u64 t, %1; cvt.u32.u64 %0, t; }"
        : "=r"(a) : "l"(p));
    return a;
}
__device__ __forceinline__ void ldmA(uint32_t a[4], uint32_t addr) {
    asm volatile("ldmatrix.sync.aligned.m8n8.x4.shared.b16 {%0,%1,%2,%3}, [%4];"
                 : "=r"(a[0]), "=r"(a[1]), "=r"(a[2]), "=r"(a[3]) : "r"(addr));
}
__device__ __forceinline__ void mma16816(float c[4], const uint32_t a[4],
                                         uint32_t b0, uint32_t b1) {
    asm volatile("mma.sync.aligned.m16n8k16.row.col.f32.f16.f16.f32 "
                 "{%0,%1,%2,%3}, {%4,%5,%6,%7}, {%8,%9}, {%0,%1,%2,%3};"
                 : "+f"(c[0]), "+f"(c[1]), "+f"(c[2]), "+f"(c[3])
                 : "r"(a[0]), "r"(a[1]), "r"(a[2]), "r"(a[3]), "r"(b0), "r"(b1));
}
__device__ __forceinline__ uint32_t packh2(float lo, float hi) {
    __half2 h = __floats2half2_rn(lo, hi);
    uint32_t u; memcpy(&u, &h, 4); return u;
}

// ---------------------------------------------------------------------------
// prepack: W (fp32 [K][N] row-major) -> per-lane mma B fragment uint4 image.
// (layout verified by round-5 pass)
// ---------------------------------------------------------------------------
extern "C" __global__ void pivnet_prepack(
    const float* __restrict__ W1, const float* __restrict__ W2,
    const float* __restrict__ W3, const float* __restrict__ W4)
{
    for (int u = blockIdx.x * blockDim.x + threadIdx.x; u < IMG_U4;
         u += gridDim.x * blockDim.x) {
        const float* W; int Ksrc, Nsrc, stride, npairs, lu;
        if (u < OFF2)      { W = W1; Ksrc = 105; Nsrc = 512; stride = 512; npairs = 32; lu = u - OFF1; }
        else if (u < OFF3) { W = W2; Ksrc = 512; Nsrc = 512; stride = 512; npairs = 32; lu = u - OFF2; }
        else if (u < OFF4) { W = W3; Ksrc = 512; Nsrc = 512; stride = 512; npairs = 32; lu = u - OFF3; }
        else               { W = W4; Ksrc = 512; Nsrc = 100; stride = 100; npairs = 8;  lu = u - OFF4; }
        const int PB = npairs * 32;
        const int kblk = lu / PB, rem = lu - kblk * PB;
        const int npair = rem >> 5, lane = rem & 31;
        const int g = lane >> 2, tig = lane & 3;
        const int k0 = kblk * 16 + tig * 2;
        const int na = npair * 16 + g, nb = na + 8;
        auto rd = [&](int k, int n) -> float {
            return (k < Ksrc && n < Nsrc) ? W[k * stride + n] : 0.f;
        };
        uint4 v;
        v.x = packh2(rd(k0,     na), rd(k0 + 1, na));
        v.y = packh2(rd(k0 + 8, na), rd(k0 + 9, na));
        v.z = packh2(rd(k0,     nb), rd(k0 + 1, nb));
        v.w = packh2(rd(k0 + 8, nb), rd(k0 + 9, nb));
        g_Wfrag[u] = v;
    }
}

// ---------------------------------------------------------------------------
// relu layer: warp = 32 rows x 64 cols. src/dst smem ping-pong.
//   m0 = rowg*32, c0 = colg*64 (rowg in 0..1, colg in 0..7)
// ---------------------------------------------------------------------------
template<int KSTEPS>
__device__ __forceinline__ void layer_relu(
    uint32_t srcU32, char* __restrict__ dst, const uint4* __restrict__ img,
    const float* __restrict__ bias,
    int m0, int colg, int lane, int g, int tig)
{
    const int rlo  = m0 + (lane & 7) + ((lane >> 3) & 1) * 8;
    const int colb = (lane >> 4) * 8;
    uint32_t aLoA = srcU32 + (rlo * PITCH + colb) * 2;
    uint32_t aHiA = aLoA + 16 * PITCH * 2;

    float accLo[8][4], accHi[8][4];
    #pragma unroll
    for (int f = 0; f < 8; f++)
        #pragma unroll
        for (int q = 0; q < 4; q++) { accLo[f][q] = 0.f; accHi[f][q] = 0.f; }

    const uint4* imgp = img + (colg * 4) * 32 + lane;
    #pragma unroll 2
    for (int ks = 0; ks < KSTEPS; ks++) {
        uint32_t aLo[4], aHi[4];
        ldmA(aLo, aLoA); aLoA += 32;
        ldmA(aHi, aHiA); aHiA += 32;
        #pragma unroll
        for (int p = 0; p < 4; p++) {
            const uint4 v = __ldg(imgp + p * 32);
            mma16816(accLo[2 * p],     aLo, v.x, v.y);
            mma16816(accLo[2 * p + 1], aLo, v.z, v.w);
            mma16816(accHi[2 * p],     aHi, v.x, v.y);
            mma16816(accHi[2 * p + 1], aHi, v.z, v.w);
        }
        imgp += 32 * 32;    // next kblk (PB = 1024 u4 for N=512)
    }

    #pragma unroll
    for (int f = 0; f < 8; f++) {
        const int c = colg * 64 + f * 8 + tig * 2;
        const float b0 = __ldg(bias + c), b1 = __ldg(bias + c + 1);
        *(__half2*)(dst + ((m0 + g)          * PITCH + c) * 2) =
            __floats2half2_rn(fmaxf(accLo[f][0] + b0, 0.f), fmaxf(accLo[f][1] + b1, 0.f));
        *(__half2*)(dst + ((m0 + g + 8)      * PITCH + c) * 2) =
            __floats2half2_rn(fmaxf(accLo[f][2] + b0, 0.f), fmaxf(accLo[f][3] + b1, 0.f));
        *(__half2*)(dst + ((m0 + 16 + g)     * PITCH + c) * 2) =
            __floats2half2_rn(fmaxf(accHi[f][0] + b0, 0.f), fmaxf(accHi[f][1] + b1, 0.f));
        *(__half2*)(dst + ((m0 + 16 + g + 8) * PITCH + c) * 2) =
            __floats2half2_rn(fmaxf(accHi[f][2] + b0, 0.f), fmaxf(accHi[f][3] + b1, 0.f));
    }
}

// output layer: warp = 32 rows x 16 cols (N=128 padded, store n<100)
__device__ __forceinline__ void layer_out(
    uint32_t srcU32, const uint4* __restrict__ img,
    const float* __restrict__ b4, float* __restrict__ outg,
    int m0, int colg, int lane, int g, int tig)
{
    const int rlo  = m0 + (lane & 7) + ((lane >> 3) & 1) * 8;
    const int colb = (lane >> 4) * 8;
    uint32_t aLoA = srcU32 + (rlo * PITCH + colb) * 2;
    uint32_t aHiA = aLoA + 16 * PITCH * 2;

    float accLo[2][4], accHi[2][4];
    #pragma unroll
    for (int f = 0; f < 2; f++)
        #pragma unroll
        for (int q = 0; q < 4; q++) { accLo[f][q] = 0.f; accHi[f][q] = 0.f; }

    const uint4* imgp = img + colg * 32 + lane;
    #pragma unroll 4
    for (int ks = 0; ks < 32; ks++) {
        uint32_t aLo[4], aHi[4];
        ldmA(aLo, aLoA); aLoA += 32;
        ldmA(aHi, aHiA); aHiA += 32;
        const uint4 v = __ldg(imgp);
        mma16816(accLo[0], aLo, v.x, v.y);
        mma16816(accLo[1], aLo, v.z, v.w);
        mma16816(accHi[0], aHi, v.x, v.y);
        mma16816(accHi[1], aHi, v.z, v.w);
        imgp += 8 * 32;     // PB = 256 u4
    }

    #pragma unroll
    for (int f = 0; f < 2; f++) {
        const int n = colg * 16 + f * 8 + tig * 2;
        if (n < KN) {
            const float b0 = __ldg(b4 + n), b1 = __ldg(b4 + n + 1);
            *(float2*)(outg + (m0 + g)          * KN + n) = make_float2(accLo[f][0] + b0, accLo[f][1] + b1);
            *(float2*)(outg + (m0 + g + 8)      * KN + n) = make_float2(accLo[f][2] + b0, accLo[f][3] + b1);
            *(float2*)(outg + (m0 + 16 + g)     * KN + n) = make_float2(accHi[f][0] + b0, accHi[f][1] + b1);
            *(float2*)(outg + (m0 + 16 + g + 8) * KN + n) = make_float2(accHi[f][2] + b0, accHi[f][3] + b1);
        }
    }
}

// ---------------------------------------------------------------------------
extern "C" __global__ void __launch_bounds__(THREADS, 1)
pivnet_mma(
    const float* __restrict__ x,
    const float* __restrict__ minv,  const float* __restrict__ maxv,
    const float* __restrict__ pivots, const float* __restrict__ knnd,
    const float* __restrict__ qmean, const float* __restrict__ qstd,
    const float* __restrict__ kmean, const float* __restrict__ kstd,
    const float* __restrict__ b1, const float* __restrict__ b2,
    const float* __restrict__ b3, const float* __restrict__ b4,
    float* __restrict__ out)
{
    extern __shared__ char smem[];
    char*  sA0  = smem + SM_A0;
    char*  sA1  = smem + SM_A1;
    float* sKm  = (float*)(smem + SM_KM);
    float* sKi  = (float*)(smem + SM_KI);
    int*   sIdx = (int*)(smem + SM_IDX);

    const int tid  = threadIdx.x;
    const int wid  = tid >> 5;
    const int lane = tid & 31;
    const int g    = lane >> 2;
    const int tig  = lane & 3;
    const int rowg = wid & 1;          // 2 row groups of 32
    const int colg = wid >> 1;         // 8 col groups of 64
    const int m0   = rowg * 32;

    const uint32_t a0u = smem_u32(sA0);
    const uint32_t a1u = smem_u32(sA1);

    for (int j = tid; j < KN; j += THREADS) {
        sKm[j] = kmean[j];
        sKi[j] = 1.f / kstd[j];
    }
    __syncthreads();

    for (int tile = blockIdx.x; tile < NTILES; tile += gridDim.x) {
        const int rowbase = tile * TILE_M;

        // ---- stage 0a: idx, qn, dist, zero-pad (threads 0..63) ----
        if (tid < TILE_M) {
            const int row = rowbase + tid;
            const float4 xv4 = __ldg((const float4*)x + row);
            float xs[4] = {xv4.x, xv4.y, xv4.z, xv4.w};
            int idx = 0;
            float diag2 = 0.f;
            __half* arow = (__half*)(sA0 + tid * PITCH * 2);
            #pragma unroll
            for (int d = 0; d < DIMN; d++) {
                const float mn = minv[d], mx = maxv[d];
                const float s = (xs[d] - mn) / (mx - mn) * 16.f;
                int bi = (int)floorf(s);
                bi = bi < 0 ? 0 : (bi > 15 ? 15 : bi);
                idx = (idx << 4) + bi;
                const float bw = (mx - mn) * 0.0625f;
                diag2 += bw * bw;
                arow[d] = __float2half((xs[d] - qmean[d]) / qstd[d]);
            }
            sIdx[tid] = idx;
            float d2 = 0.f;
            #pragma unroll
            for (int d = 0; d < DIMN; d++) {
                const float dd = xs[d] - pivots[idx * DIMN + d];
                d2 += dd * dd;
            }
            arow[DIMN] = __float2half(sqrtf(d2 / diag2));
            #pragma unroll
            for (int c = 105; c < 112; c++) arow[c] = __half(0.f);
        }
        __syncthreads();

        // ---- stage 0b: knnd gather ----
        for (int i = tid; i < TILE_M * KN; i += THREADS) {
            const int r = i / KN, j = i - r * KN;
            const float v = __ldg(knnd + (size_t)sIdx[r] * KN + j);
            ((__half*)(sA0 + r * PITCH * 2))[DIMN + 1 + j] =
                __float2half((v - sKm[j]) * sKi[j]);
        }
        __syncthreads();

        // ---- layers ----
        layer_relu<7> (a0u, sA1, g_Wfrag + OFF1, b1, m0, colg, lane, g, tig);
        __syncthreads();
        layer_relu<32>(a1u, sA0, g_Wfrag + OFF2, b2, m0, colg, lane, g, tig);
        __syncthreads();
        layer_relu<32>(a0u, sA1, g_Wfrag + OFF3, b3, m0, colg, lane, g, tig);
        __syncthreads();
        layer_out(a1u, g_Wfrag + OFF4, b4, out + (size_t)rowbase * KN,
                  m0, colg, lane, g, tig);
        __syncthreads();
    }
}

// ---------------------------------------------------------------------------
extern "C" void kernel_launch(void* const* d_in, const int* in_sizes, int n_in,
                              void* d_out, int out_size)
{
    const float* x     = (const float*)d_in[0];
    const float* minv  = (const float*)d_in[1];
    const float* maxv  = (const float*)d_in[2];
    const float* piv   = (const float*)d_in[3];
    const float* knnd  = (const float*)d_in[4];
    const float* qmean = (const float*)d_in[5];
    const float* qstd  = (const float*)d_in[6];
    const float* kmean = (const float*)d_in[7];
    const float* kstd  = (const float*)d_in[8];
    const float* W1    = (const float*)d_in[9];
    const float* b1    = (const float*)d_in[10];
    const float* W2    = (const float*)d_in[11];
    const float* b2    = (const float*)d_in[12];
    const float* W3    = (const float*)d_in[13];
    const float* b3    = (const float*)d_in[14];
    const float* W4    = (const float*)d_in[15];
    const float* b4    = (const float*)d_in[16];
    float* out = (float*)d_out;

    pivnet_prepack<<<256, 256>>>(W1, W2, W3, W4);

    cudaFuncSetAttribute(pivnet_mma,
                         cudaFuncAttributeMaxDynamicSharedMemorySize, SMEM_BYTES);
    pivnet_mma<<<GRID_CTAS, THREADS, SMEM_BYTES>>>(
        x, minv, maxv, piv, knnd, qmean, qstd, kmean, kstd,
        b1, b2, b3, b4, out);
}

// round 9
// speedup vs baseline: 9.4703x; 1.1261x over previous
#include <cuda_runtime.h>
#include <cuda_fp16.h>
#include <cstdint>
#include <cstring>

// ===========================================================================
// PivNet — mma.sync (HMMA), fp16 in / fp32 acc.
// Round 8: 256-thread CTAs (TILE_M=32), __launch_bounds__(256,2) -> 2 CTAs/SM
// (register-file now fits two). Cross-CTA overlap fills tensor-pipe gaps left
// by stage0 gather / epilogue / barriers. Biases cached in smem.
// ===========================================================================

#define B_TOTAL   524288
#define DIMN      4
#define KN        100
#define TILE_M    32
#define THREADS   256
#define NTILES    (B_TOTAL / TILE_M)   // 16384
#define GRID_CTAS 304
#define PITCH     520                  // halfs

// fragment image offsets (uint4 units) — layout identical to round 5/6 (verified)
#define OFF1 0                          // W1: K=112(pad) x N=512
#define OFF2 7168
#define OFF3 39936
#define OFF4 72704                      // W4: K=512 x N=128(pad)
#define IMG_U4 80896

__device__ __align__(16) uint4 g_Wfrag[IMG_U4];

// smem layout (bytes)
#define SM_BUF_BYTES (TILE_M * PITCH * 2)    // 33280
#define SM_A0   0
#define SM_A1   SM_BUF_BYTES
#define SM_KM   (2 * SM_BUF_BYTES)           // 100 floats
#define SM_KI   (SM_KM + 400)                // 100 floats
#define SM_IDX  (SM_KI + 400)                // 32 ints
#define SM_B1   (SM_IDX + 128)
#define SM_B2   (SM_B1 + 2048)
#define SM_B3   (SM_B2 + 2048)
#define SM_B4   (SM_B3 + 2048)               // 128 floats (pad)
#define SMEM_BYTES (SM_B4 + 512 + 32)

// ---------------------------------------------------------------------------
__device__ __forceinline__ uint32_t smem_u32(const void* p) {
    uint32_t a;
    asm("{ .reg .u64 t; cvta.to.shared.u64 t, %1; cvt.u32.u64 %0, t; }"
        : "=r"(a) : "l"(p));
    return a;
}
__device__ __forceinline__ void ldmA(uint32_t a[4], uint32_t addr) {
    asm volatile("ldmatrix.sync.aligned.m8n8.x4.shared.b16 {%0,%1,%2,%3}, [%4];"
                 : "=r"(a[0]), "=r"(a[1]), "=r"(a[2]), "=r"(a[3]) : "r"(addr));
}
__device__ __forceinline__ void mma16816(float c[4], const uint32_t a[4],
                                         uint32_t b0, uint32_t b1) {
    asm volatile("mma.sync.aligned.m16n8k16.row.col.f32.f16.f16.f32 "
                 "{%0,%1,%2,%3}, {%4,%5,%6,%7}, {%8,%9}, {%0,%1,%2,%3};"
                 : "+f"(c[0]), "+f"(c[1]), "+f"(c[2]), "+f"(c[3])
                 : "r"(a[0]), "r"(a[1]), "r"(a[2]), "r"(a[3]), "r"(b0), "r"(b1));
}
__device__ __forceinline__ uint32_t packh2(float lo, float hi) {
    __half2 h = __floats2half2_rn(lo, hi);
    uint32_t u; memcpy(&u, &h, 4); return u;
}

// ---------------------------------------------------------------------------
// prepack: W (fp32 [K][N] row-major) -> per-lane mma B fragment uint4 image.
// ---------------------------------------------------------------------------
extern "C" __global__ void pivnet_prepack(
    const float* __restrict__ W1, const float* __restrict__ W2,
    const float* __restrict__ W3, const float* __restrict__ W4)
{
    for (int u = blockIdx.x * blockDim.x + threadIdx.x; u < IMG_U4;
         u += gridDim.x * blockDim.x) {
        const float* W; int Ksrc, Nsrc, stride, npairs, lu;
        if (u < OFF2)      { W = W1; Ksrc = 105; Nsrc = 512; stride = 512; npairs = 32; lu = u - OFF1; }
        else if (u < OFF3) { W = W2; Ksrc = 512; Nsrc = 512; stride = 512; npairs = 32; lu = u - OFF2; }
        else if (u < OFF4) { W = W3; Ksrc = 512; Nsrc = 512; stride = 512; npairs = 32; lu = u - OFF3; }
        else               { W = W4; Ksrc = 512; Nsrc = 100; stride = 100; npairs = 8;  lu = u - OFF4; }
        const int PB = npairs * 32;
        const int kblk = lu / PB, rem = lu - kblk * PB;
        const int npair = rem >> 5, lane = rem & 31;
        const int g = lane >> 2, tig = lane & 3;
        const int k0 = kblk * 16 + tig * 2;
        const int na = npair * 16 + g, nb = na + 8;
        auto rd = [&](int k, int n) -> float {
            return (k < Ksrc && n < Nsrc) ? W[k * stride + n] : 0.f;
        };
        uint4 v;
        v.x = packh2(rd(k0,     na), rd(k0 + 1, na));
        v.y = packh2(rd(k0 + 8, na), rd(k0 + 9, na));
        v.z = packh2(rd(k0,     nb), rd(k0 + 1, nb));
        v.w = packh2(rd(k0 + 8, nb), rd(k0 + 9, nb));
        g_Wfrag[u] = v;
    }
}

// ---------------------------------------------------------------------------
// relu layer: warp = all 32 rows x 64 cols (colg = wid, 8 warps cover N=512).
// ---------------------------------------------------------------------------
template<int KSTEPS>
__device__ __forceinline__ void layer_relu(
    uint32_t srcU32, char* __restrict__ dst, const uint4* __restrict__ img,
    const float* __restrict__ biasS,          // smem
    int colg, int lane, int g, int tig)
{
    const int rlo  = (lane & 7) + ((lane >> 3) & 1) * 8;
    const int colb = (lane >> 4) * 8;
    uint32_t aLoA = srcU32 + (rlo * PITCH + colb) * 2;
    uint32_t aHiA = aLoA + 16 * PITCH * 2;

    float accLo[8][4], accHi[8][4];
    #pragma unroll
    for (int f = 0; f < 8; f++)
        #pragma unroll
        for (int q = 0; q < 4; q++) { accLo[f][q] = 0.f; accHi[f][q] = 0.f; }

    const uint4* imgp = img + (colg * 4) * 32 + lane;
    #pragma unroll 2
    for (int ks = 0; ks < KSTEPS; ks++) {
        uint32_t aLo[4], aHi[4];
        ldmA(aLo, aLoA); aLoA += 32;
        ldmA(aHi, aHiA); aHiA += 32;
        #pragma unroll
        for (int p = 0; p < 4; p++) {
            const uint4 v = __ldg(imgp + p * 32);
            mma16816(accLo[2 * p],     aLo, v.x, v.y);
            mma16816(accLo[2 * p + 1], aLo, v.z, v.w);
            mma16816(accHi[2 * p],     aHi, v.x, v.y);
            mma16816(accHi[2 * p + 1], aHi, v.z, v.w);
        }
        imgp += 32 * 32;    // next kblk (PB = 1024 u4 for N=512)
    }

    #pragma unroll
    for (int f = 0; f < 8; f++) {
        const int c = colg * 64 + f * 8 + tig * 2;
        const float b0 = biasS[c], b1 = biasS[c + 1];
        *(__half2*)(dst + ((g)          * PITCH + c) * 2) =
            __floats2half2_rn(fmaxf(accLo[f][0] + b0, 0.f), fmaxf(accLo[f][1] + b1, 0.f));
        *(__half2*)(dst + ((g + 8)      * PITCH + c) * 2) =
            __floats2half2_rn(fmaxf(accLo[f][2] + b0, 0.f), fmaxf(accLo[f][3] + b1, 0.f));
        *(__half2*)(dst + ((16 + g)     * PITCH + c) * 2) =
            __floats2half2_rn(fmaxf(accHi[f][0] + b0, 0.f), fmaxf(accHi[f][1] + b1, 0.f));
        *(__half2*)(dst + ((16 + g + 8) * PITCH + c) * 2) =
            __floats2half2_rn(fmaxf(accHi[f][2] + b0, 0.f), fmaxf(accHi[f][3] + b1, 0.f));
    }
}

// output layer: warp = 32 rows x 16 cols (8 warps cover N=128 pad; store n<100)
__device__ __forceinline__ void layer_out(
    uint32_t srcU32, const uint4* __restrict__ img,
    const float* __restrict__ b4S, float* __restrict__ outg,
    int colg, int lane, int g, int tig)
{
    const int rlo  = (lane & 7) + ((lane >> 3) & 1) * 8;
    const int colb = (lane >> 4) * 8;
    uint32_t aLoA = srcU32 + (rlo * PITCH + colb) * 2;
    uint32_t aHiA = aLoA + 16 * PITCH * 2;

    float accLo[2][4], accHi[2][4];
    #pragma unroll
    for (int f = 0; f < 2; f++)
        #pragma unroll
        for (int q = 0; q < 4; q++) { accLo[f][q] = 0.f; accHi[f][q] = 0.f; }

    const uint4* imgp = img + colg * 32 + lane;
    #pragma unroll 4
    for (int ks = 0; ks < 32; ks++) {
        uint32_t aLo[4], aHi[4];
        ldmA(aLo, aLoA); aLoA += 32;
        ldmA(aHi, aHiA); aHiA += 32;
        const uint4 v = __ldg(imgp);
        mma16816(accLo[0], aLo, v.x, v.y);
        mma16816(accLo[1], aLo, v.z, v.w);
        mma16816(accHi[0], aHi, v.x, v.y);
        mma16816(accHi[1], aHi, v.z, v.w);
        imgp += 8 * 32;     // PB = 256 u4
    }

    #pragma unroll
    for (int f = 0; f < 2; f++) {
        const int n = colg * 16 + f * 8 + tig * 2;
        if (n < KN) {
            const float b0 = b4S[n], b1 = b4S[n + 1];
            *(float2*)(outg + (g)          * KN + n) = make_float2(accLo[f][0] + b0, accLo[f][1] + b1);
            *(float2*)(outg + (g + 8)      * KN + n) = make_float2(accLo[f][2] + b0, accLo[f][3] + b1);
            *(float2*)(outg + (16 + g)     * KN + n) = make_float2(accHi[f][0] + b0, accHi[f][1] + b1);
            *(float2*)(outg + (16 + g + 8) * KN + n) = make_float2(accHi[f][2] + b0, accHi[f][3] + b1);
        }
    }
}

// ---------------------------------------------------------------------------
extern "C" __global__ void __launch_bounds__(THREADS, 2)
pivnet_mma(
    const float* __restrict__ x,
    const float* __restrict__ minv,  const float* __restrict__ maxv,
    const float* __restrict__ pivots, const float* __restrict__ knnd,
    const float* __restrict__ qmean, const float* __restrict__ qstd,
    const float* __restrict__ kmean, const float* __restrict__ kstd,
    const float* __restrict__ b1, const float* __restrict__ b2,
    const float* __restrict__ b3, const float* __restrict__ b4,
    float* __restrict__ out)
{
    extern __shared__ char smem[];
    char*  sA0  = smem + SM_A0;
    char*  sA1  = smem + SM_A1;
    float* sKm  = (float*)(smem + SM_KM);
    float* sKi  = (float*)(smem + SM_KI);
    int*   sIdx = (int*)(smem + SM_IDX);
    float* sB1  = (float*)(smem + SM_B1);
    float* sB2  = (float*)(smem + SM_B2);
    float* sB3  = (float*)(smem + SM_B3);
    float* sB4  = (float*)(smem + SM_B4);

    const int tid  = threadIdx.x;
    const int wid  = tid >> 5;
    const int lane = tid & 31;
    const int g    = lane >> 2;
    const int tig  = lane & 3;
    const int colg = wid;              // 8 col groups of 64

    const uint32_t a0u = smem_u32(sA0);
    const uint32_t a1u = smem_u32(sA1);

    for (int j = tid; j < KN; j += THREADS) {
        sKm[j] = kmean[j];
        sKi[j] = 1.f / kstd[j];
    }
    for (int j = tid; j < 512; j += THREADS) {
        sB1[j] = b1[j];
        sB2[j] = b2[j];
        sB3[j] = b3[j];
        if (j < 128) sB4[j] = (j < KN) ? b4[j] : 0.f;
    }
    __syncthreads();

    for (int tile = blockIdx.x; tile < NTILES; tile += gridDim.x) {
        const int rowbase = tile * TILE_M;

        // ---- stage 0a: idx, qn, dist, zero-pad (threads 0..31) ----
        if (tid < TILE_M) {
            const int row = rowbase + tid;
            const float4 xv4 = __ldg((const float4*)x + row);
            float xs[4] = {xv4.x, xv4.y, xv4.z, xv4.w};
            int idx = 0;
            float diag2 = 0.f;
            __half* arow = (__half*)(sA0 + tid * PITCH * 2);
            #pragma unroll
            for (int d = 0; d < DIMN; d++) {
                const float mn = minv[d], mx = maxv[d];
                const float s = (xs[d] - mn) / (mx - mn) * 16.f;
                int bi = (int)floorf(s);
                bi = bi < 0 ? 0 : (bi > 15 ? 15 : bi);
                idx = (idx << 4) + bi;
                const float bw = (mx - mn) * 0.0625f;
                diag2 += bw * bw;
                arow[d] = __float2half((xs[d] - qmean[d]) / qstd[d]);
            }
            sIdx[tid] = idx;
            float d2 = 0.f;
            #pragma unroll
            for (int d = 0; d < DIMN; d++) {
                const float dd = xs[d] - pivots[idx * DIMN + d];
                d2 += dd * dd;
            }
            arow[DIMN] = __float2half(sqrtf(d2 / diag2));
            #pragma unroll
            for (int c = 105; c < 112; c++) arow[c] = __half(0.f);
        }
        __syncthreads();

        // ---- stage 0b: knnd gather ----
        for (int i = tid; i < TILE_M * KN; i += THREADS) {
            const int r = i / KN, j = i - r * KN;
            const float v = __ldg(knnd + (size_t)sIdx[r] * KN + j);
            ((__half*)(sA0 + r * PITCH * 2))[DIMN + 1 + j] =
                __float2half((v - sKm[j]) * sKi[j]);
        }
        __syncthreads();

        // ---- layers ----
        layer_relu<7> (a0u, sA1, g_Wfrag + OFF1, sB1, colg, lane, g, tig);
        __syncthreads();
        layer_relu<32>(a1u, sA0, g_Wfrag + OFF2, sB2, colg, lane, g, tig);
        __syncthreads();
        layer_relu<32>(a0u, sA1, g_Wfrag + OFF3, sB3, colg, lane, g, tig);
        __syncthreads();
        layer_out(a1u, g_Wfrag + OFF4, sB4, out + (size_t)rowbase * KN,
                  colg, lane, g, tig);
        __syncthreads();
    }
}

// ---------------------------------------------------------------------------
extern "C" void kernel_launch(void* const* d_in, const int* in_sizes, int n_in,
                              void* d_out, int out_size)
{
    const float* x     = (const float*)d_in[0];
    const float* minv  = (const float*)d_in[1];
    const float* maxv  = (const float*)d_in[2];
    const float* piv   = (const float*)d_in[3];
    const float* knnd  = (const float*)d_in[4];
    const float* qmean = (const float*)d_in[5];
    const float* qstd  = (const float*)d_in[6];
    const float* kmean = (const float*)d_in[7];
    const float* kstd  = (const float*)d_in[8];
    const float* W1    = (const float*)d_in[9];
    const float* b1    = (const float*)d_in[10];
    const float* W2    = (const float*)d_in[11];
    const float* b2    = (const float*)d_in[12];
    const float* W3    = (const float*)d_in[13];
    const float* b3    = (const float*)d_in[14];
    const float* W4    = (const float*)d_in[15];
    const float* b4    = (const float*)d_in[16];
    float* out = (float*)d_out;

    pivnet_prepack<<<256, 256>>>(W1, W2, W3, W4);

    cudaFuncSetAttribute(pivnet_mma,
                         cudaFuncAttributeMaxDynamicSharedMemorySize, SMEM_BYTES);
    pivnet_mma<<<GRID_CTAS, THREADS, SMEM_BYTES>>>(
        x, minv, maxv, piv, knnd, qmean, qstd, kmean, kstd,
        b1, b2, b3, b4, out);
}

// round 10
// speedup vs baseline: 9.6974x; 1.0240x over previous
#include <cuda_runtime.h>
#include <cuda_fp16.h>
#include <cstdint>
#include <cstring>

// ===========================================================================
// PivNet — mma.sync (HMMA), fp16 in / fp32 acc.
// Round 10: cross-tile software pipeline. While tile t's layer_out runs,
// warp 0 computes tile t+1's grid-hash and fires cp.async.cg for the raw
// knnd rows; normalize happens post-wait. Features live in small dedicated
// double buffers. 2 CTAs/SM as in round 8/9.
// ===========================================================================

#define B_TOTAL   524288
#define DIMN      4
#define KN        100
#define TILE_M    32
#define THREADS   256
#define NTILES    (B_TOTAL / TILE_M)   // 16384
#define GRID_CTAS 304
#define PITCH_H   520                  // halfs
#define PITCH_F   120                  // halfs (240B rows, 16B aligned, conflict-free)

// fragment image offsets (uint4 units) — layout verified in rounds 5-9
#define OFF1 0
#define OFF2 7168
#define OFF3 39936
#define OFF4 72704
#define IMG_U4 80896

__device__ __align__(16) uint4 g_Wfrag[IMG_U4];

// smem layout (bytes)
#define SM_H0    0
#define SM_H1    33280
#define SM_F0    66560                 // 32 x 120 halfs = 7680
#define SM_F1    74240
#define SM_RAW   81920                 // 32 x 400B raw knnd rows = 12800
#define SM_B1    94720
#define SM_B2    96768
#define SM_B3    98816
#define SM_B4    100864                // 128 floats
#define SM_KM    101376                // 100 floats
#define SM_KI    101776
#define SMEM_BYTES 102400

// ---------------------------------------------------------------------------
__device__ __forceinline__ uint32_t smem_u32(const void* p) {
    uint32_t a;
    asm("{ .reg .u64 t; cvta.to.shared.u64 t, %1; cvt.u32.u64 %0, t; }"
        : "=r"(a) : "l"(p));
    return a;
}
__device__ __forceinline__ void ldmA(uint32_t a[4], uint32_t addr) {
    asm volatile("ldmatrix.sync.aligned.m8n8.x4.shared.b16 {%0,%1,%2,%3}, [%4];"
                 : "=r"(a[0]), "=r"(a[1]), "=r"(a[2]), "=r"(a[3]) : "r"(addr));
}
__device__ __forceinline__ void mma16816(float c[4], const uint32_t a[4],
                                         uint32_t b0, uint32_t b1) {
    asm volatile("mma.sync.aligned.m16n8k16.row.col.f32.f16.f16.f32 "
                 "{%0,%1,%2,%3}, {%4,%5,%6,%7}, {%8,%9}, {%0,%1,%2,%3};"
                 : "+f"(c[0]), "+f"(c[1]), "+f"(c[2]), "+f"(c[3])
                 : "r"(a[0]), "r"(a[1]), "r"(a[2]), "r"(a[3]), "r"(b0), "r"(b1));
}
__device__ __forceinline__ uint32_t packh2(float lo, float hi) {
    __half2 h = __floats2half2_rn(lo, hi);
    uint32_t u; memcpy(&u, &h, 4); return u;
}
__device__ __forceinline__ void cpasync16(uint32_t saddr, const void* g) {
    asm volatile("cp.async.cg.shared.global [%0], [%1], 16;"
                 :: "r"(saddr), "l"(g) : "memory");
}
#define CP_COMMIT() asm volatile("cp.async.commit_group;" ::: "memory")
#define CP_WAIT0()  asm volatile("cp.async.wait_group 0;" ::: "memory")

// ---------------------------------------------------------------------------
// prepack: W (fp32 [K][N] row-major) -> per-lane mma B fragment uint4 image.
// ---------------------------------------------------------------------------
extern "C" __global__ void pivnet_prepack(
    const float* __restrict__ W1, const float* __restrict__ W2,
    const float* __restrict__ W3, const float* __restrict__ W4)
{
    for (int u = blockIdx.x * blockDim.x + threadIdx.x; u < IMG_U4;
         u += gridDim.x * blockDim.x) {
        const float* W; int Ksrc, Nsrc, stride, npairs, lu;
        if (u < OFF2)      { W = W1; Ksrc = 105; Nsrc = 512; stride = 512; npairs = 32; lu = u - OFF1; }
        else if (u < OFF3) { W = W2; Ksrc = 512; Nsrc = 512; stride = 512; npairs = 32; lu = u - OFF2; }
        else if (u < OFF4) { W = W3; Ksrc = 512; Nsrc = 512; stride = 512; npairs = 32; lu = u - OFF3; }
        else               { W = W4; Ksrc = 512; Nsrc = 100; stride = 100; npairs = 8;  lu = u - OFF4; }
        const int PB = npairs * 32;
        const int kblk = lu / PB, rem = lu - kblk * PB;
        const int npair = rem >> 5, lane = rem & 31;
        const int g = lane >> 2, tig = lane & 3;
        const int k0 = kblk * 16 + tig * 2;
        const int na = npair * 16 + g, nb = na + 8;
        auto rd = [&](int k, int n) -> float {
            return (k < Ksrc && n < Nsrc) ? W[k * stride + n] : 0.f;
        };
        uint4 v;
        v.x = packh2(rd(k0,     na), rd(k0 + 1, na));
        v.y = packh2(rd(k0 + 8, na), rd(k0 + 9, na));
        v.z = packh2(rd(k0,     nb), rd(k0 + 1, nb));
        v.w = packh2(rd(k0 + 8, nb), rd(k0 + 9, nb));
        g_Wfrag[u] = v;
    }
}

// ---------------------------------------------------------------------------
// relu layer: warp = 32 rows x 64 cols (colg = wid).
// ---------------------------------------------------------------------------
template<int KSTEPS, int PITCH>
__device__ __forceinline__ void layer_relu(
    uint32_t srcU32, char* __restrict__ dst, const uint4* __restrict__ img,
    const float* __restrict__ biasS,
    int colg, int lane, int g, int tig)
{
    const int rlo  = (lane & 7) + ((lane >> 3) & 1) * 8;
    const int colb = (lane >> 4) * 8;
    uint32_t aLoA = srcU32 + (rlo * PITCH + colb) * 2;
    uint32_t aHiA = aLoA + 16 * PITCH * 2;

    float accLo[8][4], accHi[8][4];
    #pragma unroll
    for (int f = 0; f < 8; f++)
        #pragma unroll
        for (int q = 0; q < 4; q++) { accLo[f][q] = 0.f; accHi[f][q] = 0.f; }

    const uint4* imgp = img + (colg * 4) * 32 + lane;
    #pragma unroll 2
    for (int ks = 0; ks < KSTEPS; ks++) {
        uint32_t aLo[4], aHi[4];
        ldmA(aLo, aLoA); aLoA += 32;
        ldmA(aHi, aHiA); aHiA += 32;
        #pragma unroll
        for (int p = 0; p < 4; p++) {
            const uint4 v = __ldg(imgp + p * 32);
            mma16816(accLo[2 * p],     aLo, v.x, v.y);
            mma16816(accLo[2 * p + 1], aLo, v.z, v.w);
            mma16816(accHi[2 * p],     aHi, v.x, v.y);
            mma16816(accHi[2 * p + 1], aHi, v.z, v.w);
        }
        imgp += 32 * 32;
    }

    #pragma unroll
    for (int f = 0; f < 8; f++) {
        const int c = colg * 64 + f * 8 + tig * 2;
        const float b0 = biasS[c], b1 = biasS[c + 1];
        *(__half2*)(dst + ((g)          * PITCH_H + c) * 2) =
            __floats2half2_rn(fmaxf(accLo[f][0] + b0, 0.f), fmaxf(accLo[f][1] + b1, 0.f));
        *(__half2*)(dst + ((g + 8)      * PITCH_H + c) * 2) =
            __floats2half2_rn(fmaxf(accLo[f][2] + b0, 0.f), fmaxf(accLo[f][3] + b1, 0.f));
        *(__half2*)(dst + ((16 + g)     * PITCH_H + c) * 2) =
            __floats2half2_rn(fmaxf(accHi[f][0] + b0, 0.f), fmaxf(accHi[f][1] + b1, 0.f));
        *(__half2*)(dst + ((16 + g + 8) * PITCH_H + c) * 2) =
            __floats2half2_rn(fmaxf(accHi[f][2] + b0, 0.f), fmaxf(accHi[f][3] + b1, 0.f));
    }
}

// output layer: warp = 32 rows x 16 cols
__device__ __forceinline__ void layer_out(
    uint32_t srcU32, const uint4* __restrict__ img,
    const float* __restrict__ b4S, float* __restrict__ outg,
    int colg, int lane, int g, int tig)
{
    const int rlo  = (lane & 7) + ((lane >> 3) & 1) * 8;
    const int colb = (lane >> 4) * 8;
    uint32_t aLoA = srcU32 + (rlo * PITCH_H + colb) * 2;
    uint32_t aHiA = aLoA + 16 * PITCH_H * 2;

    float accLo[2][4], accHi[2][4];
    #pragma unroll
    for (int f = 0; f < 2; f++)
        #pragma unroll
        for (int q = 0; q < 4; q++) { accLo[f][q] = 0.f; accHi[f][q] = 0.f; }

    const uint4* imgp = img + colg * 32 + lane;
    #pragma unroll 4
    for (int ks = 0; ks < 32; ks++) {
        uint32_t aLo[4], aHi[4];
        ldmA(aLo, aLoA); aLoA += 32;
        ldmA(aHi, aHiA); aHiA += 32;
        const uint4 v = __ldg(imgp);
        mma16816(accLo[0], aLo, v.x, v.y);
        mma16816(accLo[1], aLo, v.z, v.w);
        mma16816(accHi[0], aHi, v.x, v.y);
        mma16816(accHi[1], aHi, v.z, v.w);
        imgp += 8 * 32;
    }

    #pragma unroll
    for (int f = 0; f < 2; f++) {
        const int n = colg * 16 + f * 8 + tig * 2;
        if (n < KN) {
            const float b0 = b4S[n], b1 = b4S[n + 1];
            *(float2*)(outg + (g)          * KN + n) = make_float2(accLo[f][0] + b0, accLo[f][1] + b1);
            *(float2*)(outg + (g + 8)      * KN + n) = make_float2(accLo[f][2] + b0, accLo[f][3] + b1);
            *(float2*)(outg + (16 + g)     * KN + n) = make_float2(accHi[f][0] + b0, accHi[f][1] + b1);
            *(float2*)(outg + (16 + g + 8) * KN + n) = make_float2(accHi[f][2] + b0, accHi[f][3] + b1);
        }
    }
}

// ---------------------------------------------------------------------------
// stage0a for one tile (threads 0..31): idx, qn, dist into Fn; cp.async the
// raw knnd row into sRaw. One commit per issuing thread.
// ---------------------------------------------------------------------------
__device__ __forceinline__ void stage0a_issue(
    int rowbase, char* __restrict__ Fn, uint32_t rawU32,
    const float* __restrict__ x,
    const float* __restrict__ minv, const float* __restrict__ maxv,
    const float* __restrict__ pivots, const float* __restrict__ knnd,
    const float* __restrict__ qmean, const float* __restrict__ qstd,
    int t)   // t = lane id 0..31
{
    const int row = rowbase + t;
    const float4 xv4 = __ldg((const float4*)x + row);
    float xs[4] = {xv4.x, xv4.y, xv4.z, xv4.w};
    int idx = 0;
    float diag2 = 0.f;
    __half* arow = (__half*)(Fn + t * PITCH_F * 2);
    #pragma unroll
    for (int d = 0; d < DIMN; d++) {
        const float mn = minv[d], mx = maxv[d];
        const float s = (xs[d] - mn) / (mx - mn) * 16.f;
        int bi = (int)floorf(s);
        bi = bi < 0 ? 0 : (bi > 15 ? 15 : bi);
        idx = (idx << 4) + bi;
        const float bw = (mx - mn) * 0.0625f;
        diag2 += bw * bw;
        arow[d] = __float2half((xs[d] - qmean[d]) / qstd[d]);
    }
    float d2 = 0.f;
    #pragma unroll
    for (int d = 0; d < DIMN; d++) {
        const float dd = xs[d] - pivots[idx * DIMN + d];
        d2 += dd * dd;
    }
    arow[DIMN] = __float2half(sqrtf(d2 / diag2));

    const char* src = (const char*)(knnd + (size_t)idx * KN);
    const uint32_t dst = rawU32 + t * 400;
    #pragma unroll
    for (int i = 0; i < 25; i++)
        cpasync16(dst + i * 16, src + i * 16);
    CP_COMMIT();
}

// normalize raw rows -> Fn fp16 (all 256 threads)
__device__ __forceinline__ void normalize_raw(
    const char* __restrict__ sRaw, char* __restrict__ Fn,
    const float* __restrict__ sKm, const float* __restrict__ sKi, int tid)
{
    for (int i = tid; i < TILE_M * KN; i += THREADS) {
        const int r = i / KN, j = i - r * KN;
        const float v = ((const float*)(sRaw + r * 400))[j];
        ((__half*)(Fn + r * PITCH_F * 2))[DIMN + 1 + j] =
            __float2half((v - sKm[j]) * sKi[j]);
    }
}

// ---------------------------------------------------------------------------
extern "C" __global__ void __launch_bounds__(THREADS, 2)
pivnet_mma(
    const float* __restrict__ x,
    const float* __restrict__ minv,  const float* __restrict__ maxv,
    const float* __restrict__ pivots, const float* __restrict__ knnd,
    const float* __restrict__ qmean, const float* __restrict__ qstd,
    const float* __restrict__ kmean, const float* __restrict__ kstd,
    const float* __restrict__ b1, const float* __restrict__ b2,
    const float* __restrict__ b3, const float* __restrict__ b4,
    float* __restrict__ out)
{
    extern __shared__ char smem[];
    char*  sH0  = smem + SM_H0;
    char*  sH1  = smem + SM_H1;
    char*  sRaw = smem + SM_RAW;
    float* sB1  = (float*)(smem + SM_B1);
    float* sB2  = (float*)(smem + SM_B2);
    float* sB3  = (float*)(smem + SM_B3);
    float* sB4  = (float*)(smem + SM_B4);
    float* sKm  = (float*)(smem + SM_KM);
    float* sKi  = (float*)(smem + SM_KI);

    const int tid  = threadIdx.x;
    const int wid  = tid >> 5;
    const int lane = tid & 31;
    const int g    = lane >> 2;
    const int tig  = lane & 3;
    const int colg = wid;

    const uint32_t h0u  = smem_u32(sH0);
    const uint32_t h1u  = smem_u32(sH1);
    const uint32_t rawU = smem_u32(sRaw);

    char* Fc = smem + SM_F0;
    char* Fn = smem + SM_F1;

    for (int j = tid; j < KN; j += THREADS) {
        sKm[j] = kmean[j];
        sKi[j] = 1.f / kstd[j];
    }
    for (int j = tid; j < 512; j += THREADS) {
        sB1[j] = b1[j];
        sB2[j] = b2[j];
        sB3[j] = b3[j];
        if (j < 128) sB4[j] = (j < KN) ? b4[j] : 0.f;
    }
    // zero both F buffers once (pad cols 105..119 stay zero forever)
    for (int j = tid * 16; j < 2 * TILE_M * PITCH_F * 2; j += THREADS * 16)
        *(uint4*)(smem + SM_F0 + j) = make_uint4(0, 0, 0, 0);
    __syncthreads();

    // ---- prologue: stage0 for first tile into Fc ----
    const int tile0 = blockIdx.x;
    if (tile0 < NTILES) {
        if (tid < TILE_M)
            stage0a_issue(tile0 * TILE_M, Fc, rawU, x, minv, maxv, pivots,
                          knnd, qmean, qstd, tid);
        CP_WAIT0();
        __syncthreads();
        normalize_raw(sRaw, Fc, sKm, sKi, tid);
        __syncthreads();
    }

    for (int tile = tile0; tile < NTILES; tile += gridDim.x) {
        const int rowbase = tile * TILE_M;
        const int ntile = tile + gridDim.x;

        layer_relu<7, PITCH_F>(smem_u32(Fc), sH0, g_Wfrag + OFF1, sB1,
                               colg, lane, g, tig);
        __syncthreads();
        layer_relu<32, PITCH_H>(h0u, sH1, g_Wfrag + OFF2, sB2,
                                colg, lane, g, tig);
        __syncthreads();
        layer_relu<32, PITCH_H>(h1u, sH0, g_Wfrag + OFF3, sB3,
                                colg, lane, g, tig);
        __syncthreads();

        // warp 0: prefetch next tile's features while others run layer_out
        if (wid == 0 && ntile < NTILES)
            stage0a_issue(ntile * TILE_M, Fn, rawU, x, minv, maxv, pivots,
                          knnd, qmean, qstd, lane);

        layer_out(h0u, g_Wfrag + OFF4, sB4, out + (size_t)rowbase * KN,
                  colg, lane, g, tig);

        CP_WAIT0();
        __syncthreads();
        if (ntile < NTILES)
            normalize_raw(sRaw, Fn, sKm, sKi, tid);
        __syncthreads();

        char* t_ = Fc; Fc = Fn; Fn = t_;
    }
}

// ---------------------------------------------------------------------------
extern "C" void kernel_launch(void* const* d_in, const int* in_sizes, int n_in,
                              void* d_out, int out_size)
{
    const float* x     = (const float*)d_in[0];
    const float* minv  = (const float*)d_in[1];
    const float* maxv  = (const float*)d_in[2];
    const float* piv   = (const float*)d_in[3];
    const float* knnd  = (const float*)d_in[4];
    const float* qmean = (const float*)d_in[5];
    const float* qstd  = (const float*)d_in[6];
    const float* kmean = (const float*)d_in[7];
    const float* kstd  = (const float*)d_in[8];
    const float* W1    = (const float*)d_in[9];
    const float* b1    = (const float*)d_in[10];
    const float* W2    = (const float*)d_in[11];
    const float* b2    = (const float*)d_in[12];
    const float* W3    = (const float*)d_in[13];
    const float* b3    = (const float*)d_in[14];
    const float* W4    = (const float*)d_in[15];
    const float* b4    = (const float*)d_in[16];
    float* out = (float*)d_out;

    pivnet_prepack<<<256, 256>>>(W1, W2, W3, W4);

    cudaFuncSetAttribute(pivnet_mma,
                         cudaFuncAttributeMaxDynamicSharedMemorySize, SMEM_BYTES);
    pivnet_mma<<<GRID_CTAS, THREADS, SMEM_BYTES>>>(
        x, minv, maxv, piv, knnd, qmean, qstd, kmean, kstd,
        b1, b2, b3, b4, out);
}

// round 12
// speedup vs baseline: 10.8308x; 1.1169x over previous
#include <cuda_runtime.h>
#include <cuda_fp16.h>
#include <cstdint>
#include <cstring>

// ===========================================================================
// PivNet — mma.sync (HMMA), fp16 in / fp32 acc.
// Round 11: explicit 1-deep software pipeline on W-fragment LDGs in both
// mainloops (load ks+1's fragments before ks's mma block). Everything else
// identical to round 10 (cross-tile stage0 pipeline, 2 CTAs/SM).
// ===========================================================================

#define B_TOTAL   524288
#define DIMN      4
#define KN        100
#define TILE_M    32
#define THREADS   256
#define NTILES    (B_TOTAL / TILE_M)   // 16384
#define GRID_CTAS 304
#define PITCH_H   520                  // halfs
#define PITCH_F   120                  // halfs

// fragment image offsets (uint4 units) — layout verified in rounds 5-10
#define OFF1 0
#define OFF2 7168
#define OFF3 39936
#define OFF4 72704
#define IMG_U4 80896

__device__ __align__(16) uint4 g_Wfrag[IMG_U4];

// smem layout (bytes)
#define SM_H0    0
#define SM_H1    33280
#define SM_F0    66560
#define SM_F1    74240
#define SM_RAW   81920
#define SM_B1    94720
#define SM_B2    96768
#define SM_B3    98816
#define SM_B4    100864
#define SM_KM    101376
#define SM_KI    101776
#define SMEM_BYTES 102400

// ---------------------------------------------------------------------------
__device__ __forceinline__ uint32_t smem_u32(const void* p) {
    uint32_t a;
    asm("{ .reg .u64 t; cvta.to.shared.u64 t, %1; cvt.u32.u64 %0, t; }"
        : "=r"(a) : "l"(p));
    return a;
}
__device__ __forceinline__ void ldmA(uint32_t a[4], uint32_t addr) {
    asm volatile("ldmatrix.sync.aligned.m8n8.x4.shared.b16 {%0,%1,%2,%3}, [%4];"
                 : "=r"(a[0]), "=r"(a[1]), "=r"(a[2]), "=r"(a[3]) : "r"(addr));
}
__device__ __forceinline__ void mma16816(float c[4], const uint32_t a[4],
                                         uint32_t b0, uint32_t b1) {
    asm volatile("mma.sync.aligned.m16n8k16.row.col.f32.f16.f16.f32 "
                 "{%0,%1,%2,%3}, {%4,%5,%6,%7}, {%8,%9}, {%0,%1,%2,%3};"
                 : "+f"(c[0]), "+f"(c[1]), "+f"(c[2]), "+f"(c[3])
                 : "r"(a[0]), "r"(a[1]), "r"(a[2]), "r"(a[3]), "r"(b0), "r"(b1));
}
__device__ __forceinline__ uint32_t packh2(float lo, float hi) {
    __half2 h = __floats2half2_rn(lo, hi);
    uint32_t u; memcpy(&u, &h, 4); return u;
}
__device__ __forceinline__ void cpasync16(uint32_t saddr, const void* g) {
    asm volatile("cp.async.cg.shared.global [%0], [%1], 16;"
                 :: "r"(saddr), "l"(g) : "memory");
}
#define CP_COMMIT() asm volatile("cp.async.commit_group;" ::: "memory")
#define CP_WAIT0()  asm volatile("cp.async.wait_group 0;" ::: "memory")

// ---------------------------------------------------------------------------
// prepack: W (fp32 [K][N] row-major) -> per-lane mma B fragment uint4 image.
// ---------------------------------------------------------------------------
extern "C" __global__ void pivnet_prepack(
    const float* __restrict__ W1, const float* __restrict__ W2,
    const float* __restrict__ W3, const float* __restrict__ W4)
{
    for (int u = blockIdx.x * blockDim.x + threadIdx.x; u < IMG_U4;
         u += gridDim.x * blockDim.x) {
        const float* W; int Ksrc, Nsrc, stride, npairs, lu;
        if (u < OFF2)      { W = W1; Ksrc = 105; Nsrc = 512; stride = 512; npairs = 32; lu = u - OFF1; }
        else if (u < OFF3) { W = W2; Ksrc = 512; Nsrc = 512; stride = 512; npairs = 32; lu = u - OFF2; }
        else if (u < OFF4) { W = W3; Ksrc = 512; Nsrc = 512; stride = 512; npairs = 32; lu = u - OFF3; }
        else               { W = W4; Ksrc = 512; Nsrc = 100; stride = 100; npairs = 8;  lu = u - OFF4; }
        const int PB = npairs * 32;
        const int kblk = lu / PB, rem = lu - kblk * PB;
        const int npair = rem >> 5, lane = rem & 31;
        const int g = lane >> 2, tig = lane & 3;
        const int k0 = kblk * 16 + tig * 2;
        const int na = npair * 16 + g, nb = na + 8;
        auto rd = [&](int k, int n) -> float {
            return (k < Ksrc && n < Nsrc) ? W[k * stride + n] : 0.f;
        };
        uint4 v;
        v.x = packh2(rd(k0,     na), rd(k0 + 1, na));
        v.y = packh2(rd(k0 + 8, na), rd(k0 + 9, na));
        v.z = packh2(rd(k0,     nb), rd(k0 + 1, nb));
        v.w = packh2(rd(k0 + 8, nb), rd(k0 + 9, nb));
        g_Wfrag[u] = v;
    }
}

// ---------------------------------------------------------------------------
// relu layer with 1-deep W prefetch. warp = 32 rows x 64 cols (colg = wid).
// ---------------------------------------------------------------------------
template<int KSTEPS, int PITCH>
__device__ __forceinline__ void layer_relu(
    uint32_t srcU32, char* __restrict__ dst, const uint4* __restrict__ img,
    const float* __restrict__ biasS,
    int colg, int lane, int g, int tig)
{
    const int rlo  = (lane & 7) + ((lane >> 3) & 1) * 8;
    const int colb = (lane >> 4) * 8;
    uint32_t aLoA = srcU32 + (rlo * PITCH + colb) * 2;
    uint32_t aHiA = aLoA + 16 * PITCH * 2;

    float accLo[8][4], accHi[8][4];
    #pragma unroll
    for (int f = 0; f < 8; f++)
        #pragma unroll
        for (int q = 0; q < 4; q++) { accLo[f][q] = 0.f; accHi[f][q] = 0.f; }

    const uint4* imgp = img + (colg * 4) * 32 + lane;
    uint4 w0 = __ldg(imgp);
    uint4 w1 = __ldg(imgp + 32);
    uint4 w2 = __ldg(imgp + 64);
    uint4 w3 = __ldg(imgp + 96);
    imgp += 32 * 32;

    #pragma unroll
    for (int ks = 0; ks < KSTEPS; ks++) {
        uint4 n0, n1, n2, n3;
        if (ks + 1 < KSTEPS) {
            n0 = __ldg(imgp);
            n1 = __ldg(imgp + 32);
            n2 = __ldg(imgp + 64);
            n3 = __ldg(imgp + 96);
            imgp += 32 * 32;
        }
        uint32_t aLo[4], aHi[4];
        ldmA(aLo, aLoA); aLoA += 32;
        ldmA(aHi, aHiA); aHiA += 32;
        mma16816(accLo[0], aLo, w0.x, w0.y);
        mma16816(accLo[1], aLo, w0.z, w0.w);
        mma16816(accHi[0], aHi, w0.x, w0.y);
        mma16816(accHi[1], aHi, w0.z, w0.w);
        mma16816(accLo[2], aLo, w1.x, w1.y);
        mma16816(accLo[3], aLo, w1.z, w1.w);
        mma16816(accHi[2], aHi, w1.x, w1.y);
        mma16816(accHi[3], aHi, w1.z, w1.w);
        mma16816(accLo[4], aLo, w2.x, w2.y);
        mma16816(accLo[5], aLo, w2.z, w2.w);
        mma16816(accHi[4], aHi, w2.x, w2.y);
        mma16816(accHi[5], aHi, w2.z, w2.w);
        mma16816(accLo[6], aLo, w3.x, w3.y);
        mma16816(accLo[7], aLo, w3.z, w3.w);
        mma16816(accHi[6], aHi, w3.x, w3.y);
        mma16816(accHi[7], aHi, w3.z, w3.w);
        if (ks + 1 < KSTEPS) { w0 = n0; w1 = n1; w2 = n2; w3 = n3; }
    }

    #pragma unroll
    for (int f = 0; f < 8; f++) {
        const int c = colg * 64 + f * 8 + tig * 2;
        const float b0 = biasS[c], b1 = biasS[c + 1];
        *(__half2*)(dst + ((g)          * PITCH_H + c) * 2) =
            __floats2half2_rn(fmaxf(accLo[f][0] + b0, 0.f), fmaxf(accLo[f][1] + b1, 0.f));
        *(__half2*)(dst + ((g + 8)      * PITCH_H + c) * 2) =
            __floats2half2_rn(fmaxf(accLo[f][2] + b0, 0.f), fmaxf(accLo[f][3] + b1, 0.f));
        *(__half2*)(dst + ((16 + g)     * PITCH_H + c) * 2) =
            __floats2half2_rn(fmaxf(accHi[f][0] + b0, 0.f), fmaxf(accHi[f][1] + b1, 0.f));
        *(__half2*)(dst + ((16 + g + 8) * PITCH_H + c) * 2) =
            __floats2half2_rn(fmaxf(accHi[f][2] + b0, 0.f), fmaxf(accHi[f][3] + b1, 0.f));
    }
}

// output layer with 1-deep W prefetch: warp = 32 rows x 16 cols
__device__ __forceinline__ void layer_out(
    uint32_t srcU32, const uint4* __restrict__ img,
    const float* __restrict__ b4S, float* __restrict__ outg,
    int colg, int lane, int g, int tig)
{
    const int rlo  = (lane & 7) + ((lane >> 3) & 1) * 8;
    const int colb = (lane >> 4) * 8;
    uint32_t aLoA = srcU32 + (rlo * PITCH_H + colb) * 2;
    uint32_t aHiA = aLoA + 16 * PITCH_H * 2;

    float accLo[2][4], accHi[2][4];
    #pragma unroll
    for (int f = 0; f < 2; f++)
        #pragma unroll
        for (int q = 0; q < 4; q++) { accLo[f][q] = 0.f; accHi[f][q] = 0.f; }

    const uint4* imgp = img + colg * 32 + lane;
    uint4 w = __ldg(imgp);
    imgp += 8 * 32;

    #pragma unroll
    for (int ks = 0; ks < 32; ks++) {
        uint4 n;
        if (ks + 1 < 32) { n = __ldg(imgp); imgp += 8 * 32; }
        uint32_t aLo[4], aHi[4];
        ldmA(aLo, aLoA); aLoA += 32;
        ldmA(aHi, aHiA); aHiA += 32;
        mma16816(accLo[0], aLo, w.x, w.y);
        mma16816(accLo[1], aLo, w.z, w.w);
        mma16816(accHi[0], aHi, w.x, w.y);
        mma16816(accHi[1], aHi, w.z, w.w);
        if (ks + 1 < 32) w = n;
    }

    #pragma unroll
    for (int f = 0; f < 2; f++) {
        const int n = colg * 16 + f * 8 + tig * 2;
        if (n < KN) {
            const float b0 = b4S[n], b1 = b4S[n + 1];
            *(float2*)(outg + (g)          * KN + n) = make_float2(accLo[f][0] + b0, accLo[f][1] + b1);
            *(float2*)(outg + (g + 8)      * KN + n) = make_float2(accLo[f][2] + b0, accLo[f][3] + b1);
            *(float2*)(outg + (16 + g)     * KN + n) = make_float2(accHi[f][0] + b0, accHi[f][1] + b1);
            *(float2*)(outg + (16 + g + 8) * KN + n) = make_float2(accHi[f][2] + b0, accHi[f][3] + b1);
        }
    }
}

// ---------------------------------------------------------------------------
// stage0a: idx, qn, dist into Fn; cp.async raw knnd row into sRaw.
// ---------------------------------------------------------------------------
__device__ __forceinline__ void stage0a_issue(
    int rowbase, char* __restrict__ Fn, uint32_t rawU32,
    const float* __restrict__ x,
    const float* __restrict__ minv, const float* __restrict__ maxv,
    const float* __restrict__ pivots, const float* __restrict__ knnd,
    const float* __restrict__ qmean, const float* __restrict__ qstd,
    int t)
{
    const int row = rowbase + t;
    const float4 xv4 = __ldg((const float4*)x + row);
    float xs[4] = {xv4.x, xv4.y, xv4.z, xv4.w};
    int idx = 0;
    float diag2 = 0.f;
    __half* arow = (__half*)(Fn + t * PITCH_F * 2);
    #pragma unroll
    for (int d = 0; d < DIMN; d++) {
        const float mn = minv[d], mx = maxv[d];
        const float s = (xs[d] - mn) / (mx - mn) * 16.f;
        int bi = (int)floorf(s);
        bi = bi < 0 ? 0 : (bi > 15 ? 15 : bi);
        idx = (idx << 4) + bi;
        const float bw = (mx - mn) * 0.0625f;
        diag2 += bw * bw;
        arow[d] = __float2half((xs[d] - qmean[d]) / qstd[d]);
    }
    float d2 = 0.f;
    #pragma unroll
    for (int d = 0; d < DIMN; d++) {
        const float dd = xs[d] - pivots[idx * DIMN + d];
        d2 += dd * dd;
    }
    arow[DIMN] = __float2half(sqrtf(d2 / diag2));

    const char* src = (const char*)(knnd + (size_t)idx * KN);
    const uint32_t dst = rawU32 + t * 400;
    #pragma unroll
    for (int i = 0; i < 25; i++)
        cpasync16(dst + i * 16, src + i * 16);
    CP_COMMIT();
}

__device__ __forceinline__ void normalize_raw(
    const char* __restrict__ sRaw, char* __restrict__ Fn,
    const float* __restrict__ sKm, const float* __restrict__ sKi, int tid)
{
    for (int i = tid; i < TILE_M * KN; i += THREADS) {
        const int r = i / KN, j = i - r * KN;
        const float v = ((const float*)(sRaw + r * 400))[j];
        ((__half*)(Fn + r * PITCH_F * 2))[DIMN + 1 + j] =
            __float2half((v - sKm[j]) * sKi[j]);
    }
}

// ---------------------------------------------------------------------------
extern "C" __global__ void __launch_bounds__(THREADS, 2)
pivnet_mma(
    const float* __restrict__ x,
    const float* __restrict__ minv,  const float* __restrict__ maxv,
    const float* __restrict__ pivots, const float* __restrict__ knnd,
    const float* __restrict__ qmean, const float* __restrict__ qstd,
    const float* __restrict__ kmean, const float* __restrict__ kstd,
    const float* __restrict__ b1, const float* __restrict__ b2,
    const float* __restrict__ b3, const float* __restrict__ b4,
    float* __restrict__ out)
{
    extern __shared__ char smem[];
    char*  sH0  = smem + SM_H0;
    char*  sH1  = smem + SM_H1;
    char*  sRaw = smem + SM_RAW;
    float* sB1  = (float*)(smem + SM_B1);
    float* sB2  = (float*)(smem + SM_B2);
    float* sB3  = (float*)(smem + SM_B3);
    float* sB4  = (float*)(smem + SM_B4);
    float* sKm  = (float*)(smem + SM_KM);
    float* sKi  = (float*)(smem + SM_KI);

    const int tid  = threadIdx.x;
    const int wid  = tid >> 5;
    const int lane = tid & 31;
    const int g    = lane >> 2;
    const int tig  = lane & 3;
    const int colg = wid;

    const uint32_t h0u  = smem_u32(sH0);
    const uint32_t h1u  = smem_u32(sH1);
    const uint32_t rawU = smem_u32(sRaw);

    char* Fc = smem + SM_F0;
    char* Fn = smem + SM_F1;

    for (int j = tid; j < KN; j += THREADS) {
        sKm[j] = kmean[j];
        sKi[j] = 1.f / kstd[j];
    }
    for (int j = tid; j < 512; j += THREADS) {
        sB1[j] = b1[j];
        sB2[j] = b2[j];
        sB3[j] = b3[j];
        if (j < 128) sB4[j] = (j < KN) ? b4[j] : 0.f;
    }
    for (int j = tid * 16; j < 2 * TILE_M * PITCH_F * 2; j += THREADS * 16)
        *(uint4*)(smem + SM_F0 + j) = make_uint4(0, 0, 0, 0);
    __syncthreads();

    const int tile0 = blockIdx.x;
    if (tile0 < NTILES) {
        if (tid < TILE_M)
            stage0a_issue(tile0 * TILE_M, Fc, rawU, x, minv, maxv, pivots,
                          knnd, qmean, qstd, tid);
        CP_WAIT0();
        __syncthreads();
        normalize_raw(sRaw, Fc, sKm, sKi, tid);
        __syncthreads();
    }

    for (int tile = tile0; tile < NTILES; tile += gridDim.x) {
        const int rowbase = tile * TILE_M;
        const int ntile = tile + gridDim.x;

        layer_relu<7, PITCH_F>(smem_u32(Fc), sH0, g_Wfrag + OFF1, sB1,
                               colg, lane, g, tig);
        __syncthreads();
        layer_relu<32, PITCH_H>(h0u, sH1, g_Wfrag + OFF2, sB2,
                                colg, lane, g, tig);
        __syncthreads();
        layer_relu<32, PITCH_H>(h1u, sH0, g_Wfrag + OFF3, sB3,
                                colg, lane, g, tig);
        __syncthreads();

        if (wid == 0 && ntile < NTILES)
            stage0a_issue(ntile * TILE_M, Fn, rawU, x, minv, maxv, pivots,
                          knnd, qmean, qstd, lane);

        layer_out(h0u, g_Wfrag + OFF4, sB4, out + (size_t)rowbase * KN,
                  colg, lane, g, tig);

        CP_WAIT0();
        __syncthreads();
        if (ntile < NTILES)
            normalize_raw(sRaw, Fn, sKm, sKi, tid);
        __syncthreads();

        char* t_ = Fc; Fc = Fn; Fn = t_;
    }
}

// ---------------------------------------------------------------------------
extern "C" void kernel_launch(void* const* d_in, const int* in_sizes, int n_in,
                              void* d_out, int out_size)
{
    const float* x     = (const float*)d_in[0];
    const float* minv  = (const float*)d_in[1];
    const float* maxv  = (const float*)d_in[2];
    const float* piv   = (const float*)d_in[3];
    const float* knnd  = (const float*)d_in[4];
    const float* qmean = (const float*)d_in[5];
    const float* qstd  = (const float*)d_in[6];
    const float* kmean = (const float*)d_in[7];
    const float* kstd  = (const float*)d_in[8];
    const float* W1    = (const float*)d_in[9];
    const float* b1    = (const float*)d_in[10];
    const float* W2    = (const float*)d_in[11];
    const float* b2    = (const float*)d_in[12];
    const float* W3    = (const float*)d_in[13];
    const float* b3    = (const float*)d_in[14];
    const float* W4    = (const float*)d_in[15];
    const float* b4    = (const float*)d_in[16];
    float* out = (float*)d_out;

    pivnet_prepack<<<256, 256>>>(W1, W2, W3, W4);

    cudaFuncSetAttribute(pivnet_mma,
                         cudaFuncAttributeMaxDynamicSharedMemorySize, SMEM_BYTES);
    pivnet_mma<<<GRID_CTAS, THREADS, SMEM_BYTES>>>(
        x, minv, maxv, piv, knnd, qmean, qstd, kmean, kstd,
        b1, b2, b3, b4, out);
}

// round 13
// speedup vs baseline: 10.9070x; 1.0070x over previous
#include <cuda_runtime.h>
#include <cuda_fp16.h>
#include <cstdint>
#include <cstring>

// ===========================================================================
// PivNet — mma.sync (HMMA), fp16 in / fp32 acc.
// Round 13: cross-layer-boundary W prefetch. Each layer's mainloop ends by
// issuing the FIRST k-step W LDGs of the NEXT layer (layer4 prefetches the
// next tile's layer1), so post-barrier mainloops start with W already in
// flight ~250 cyc. Everything else = round 12.
// ===========================================================================

#define B_TOTAL   524288
#define DIMN      4
#define KN        100
#define TILE_M    32
#define THREADS   256
#define NTILES    (B_TOTAL / TILE_M)   // 16384
#define GRID_CTAS 304
#define PITCH_H   520                  // halfs
#define PITCH_F   120                  // halfs

// fragment image offsets (uint4 units) — layout verified rounds 5-12
#define OFF1 0
#define OFF2 7168
#define OFF3 39936
#define OFF4 72704
#define IMG_U4 80896

__device__ __align__(16) uint4 g_Wfrag[IMG_U4];

// smem layout (bytes)
#define SM_H0    0
#define SM_H1    33280
#define SM_F0    66560
#define SM_F1    74240
#define SM_RAW   81920
#define SM_B1    94720
#define SM_B2    96768
#define SM_B3    98816
#define SM_B4    100864
#define SM_KM    101376
#define SM_KI    101776
#define SMEM_BYTES 102400

// ---------------------------------------------------------------------------
__device__ __forceinline__ uint32_t smem_u32(const void* p) {
    uint32_t a;
    asm("{ .reg .u64 t; cvta.to.shared.u64 t, %1; cvt.u32.u64 %0, t; }"
        : "=r"(a) : "l"(p));
    return a;
}
__device__ __forceinline__ void ldmA(uint32_t a[4], uint32_t addr) {
    asm volatile("ldmatrix.sync.aligned.m8n8.x4.shared.b16 {%0,%1,%2,%3}, [%4];"
                 : "=r"(a[0]), "=r"(a[1]), "=r"(a[2]), "=r"(a[3]) : "r"(addr));
}
__device__ __forceinline__ void mma16816(float c[4], const uint32_t a[4],
                                         uint32_t b0, uint32_t b1) {
    asm volatile("mma.sync.aligned.m16n8k16.row.col.f32.f16.f16.f32 "
                 "{%0,%1,%2,%3}, {%4,%5,%6,%7}, {%8,%9}, {%0,%1,%2,%3};"
                 : "+f"(c[0]), "+f"(c[1]), "+f"(c[2]), "+f"(c[3])
                 : "r"(a[0]), "r"(a[1]), "r"(a[2]), "r"(a[3]), "r"(b0), "r"(b1));
}
__device__ __forceinline__ uint32_t packh2(float lo, float hi) {
    __half2 h = __floats2half2_rn(lo, hi);
    uint32_t u; memcpy(&u, &h, 4); return u;
}
__device__ __forceinline__ void cpasync16(uint32_t saddr, const void* g) {
    asm volatile("cp.async.cg.shared.global [%0], [%1], 16;"
                 :: "r"(saddr), "l"(g) : "memory");
}
#define CP_COMMIT() asm volatile("cp.async.commit_group;" ::: "memory")
#define CP_WAIT0()  asm volatile("cp.async.wait_group 0;" ::: "memory")

// ---------------------------------------------------------------------------
// prepack (unchanged, layout verified)
// ---------------------------------------------------------------------------
extern "C" __global__ void pivnet_prepack(
    const float* __restrict__ W1, const float* __restrict__ W2,
    const float* __restrict__ W3, const float* __restrict__ W4)
{
    for (int u = blockIdx.x * blockDim.x + threadIdx.x; u < IMG_U4;
         u += gridDim.x * blockDim.x) {
        const float* W; int Ksrc, Nsrc, stride, npairs, lu;
        if (u < OFF2)      { W = W1; Ksrc = 105; Nsrc = 512; stride = 512; npairs = 32; lu = u - OFF1; }
        else if (u < OFF3) { W = W2; Ksrc = 512; Nsrc = 512; stride = 512; npairs = 32; lu = u - OFF2; }
        else if (u < OFF4) { W = W3; Ksrc = 512; Nsrc = 512; stride = 512; npairs = 32; lu = u - OFF3; }
        else               { W = W4; Ksrc = 512; Nsrc = 100; stride = 100; npairs = 8;  lu = u - OFF4; }
        const int PB = npairs * 32;
        const int kblk = lu / PB, rem = lu - kblk * PB;
        const int npair = rem >> 5, lane = rem & 31;
        const int g = lane >> 2, tig = lane & 3;
        const int k0 = kblk * 16 + tig * 2;
        const int na = npair * 16 + g, nb = na + 8;
        auto rd = [&](int k, int n) -> float {
            return (k < Ksrc && n < Nsrc) ? W[k * stride + n] : 0.f;
        };
        uint4 v;
        v.x = packh2(rd(k0,     na), rd(k0 + 1, na));
        v.y = packh2(rd(k0 + 8, na), rd(k0 + 9, na));
        v.z = packh2(rd(k0,     nb), rd(k0 + 1, nb));
        v.w = packh2(rd(k0 + 8, nb), rd(k0 + 9, nb));
        g_Wfrag[u] = v;
    }
}

// ---------------------------------------------------------------------------
// relu layer: kstep0 W arrives preloaded (w0..w3); imgp points at kstep1.
// After the mainloop, prefetch the NEXT layer's kstep0 fragments into wout.
// ---------------------------------------------------------------------------
template<int KSTEPS, int PITCH>
__device__ __forceinline__ void layer_relu(
    uint32_t srcU32, char* __restrict__ dst, const float* __restrict__ biasS,
    int colg, int lane, int g, int tig,
    uint4 w0, uint4 w1, uint4 w2, uint4 w3,
    const uint4* __restrict__ imgp,           // kstep1 base, pre-offset
    const uint4* __restrict__ nextp,          // next layer kstep0, pre-offset
    uint4 (&wout)[4])
{
    const int rlo  = (lane & 7) + ((lane >> 3) & 1) * 8;
    const int colb = (lane >> 4) * 8;
    uint32_t aLoA = srcU32 + (rlo * PITCH + colb) * 2;
    uint32_t aHiA = aLoA + 16 * PITCH * 2;

    float accLo[8][4], accHi[8][4];
    #pragma unroll
    for (int f = 0; f < 8; f++)
        #pragma unroll
        for (int q = 0; q < 4; q++) { accLo[f][q] = 0.f; accHi[f][q] = 0.f; }

    #pragma unroll
    for (int ks = 0; ks < KSTEPS; ks++) {
        uint4 n0, n1, n2, n3;
        if (ks + 1 < KSTEPS) {
            n0 = __ldg(imgp);
            n1 = __ldg(imgp + 32);
            n2 = __ldg(imgp + 64);
            n3 = __ldg(imgp + 96);
            imgp += 32 * 32;
        }
        uint32_t aLo[4], aHi[4];
        ldmA(aLo, aLoA); aLoA += 32;
        ldmA(aHi, aHiA); aHiA += 32;
        mma16816(accLo[0], aLo, w0.x, w0.y);
        mma16816(accLo[1], aLo, w0.z, w0.w);
        mma16816(accHi[0], aHi, w0.x, w0.y);
        mma16816(accHi[1], aHi, w0.z, w0.w);
        mma16816(accLo[2], aLo, w1.x, w1.y);
        mma16816(accLo[3], aLo, w1.z, w1.w);
        mma16816(accHi[2], aHi, w1.x, w1.y);
        mma16816(accHi[3], aHi, w1.z, w1.w);
        mma16816(accLo[4], aLo, w2.x, w2.y);
        mma16816(accLo[5], aLo, w2.z, w2.w);
        mma16816(accHi[4], aHi, w2.x, w2.y);
        mma16816(accHi[5], aHi, w2.z, w2.w);
        mma16816(accLo[6], aLo, w3.x, w3.y);
        mma16816(accLo[7], aLo, w3.z, w3.w);
        mma16816(accHi[6], aHi, w3.x, w3.y);
        mma16816(accHi[7], aHi, w3.z, w3.w);
        if (ks + 1 < KSTEPS) { w0 = n0; w1 = n1; w2 = n2; w3 = n3; }
    }

    // prefetch next layer's kstep0 — flies through epilogue + barrier
    wout[0] = __ldg(nextp);
    wout[1] = __ldg(nextp + 32);
    wout[2] = __ldg(nextp + 64);
    wout[3] = __ldg(nextp + 96);

    #pragma unroll
    for (int f = 0; f < 8; f++) {
        const int c = colg * 64 + f * 8 + tig * 2;
        const float b0 = biasS[c], b1 = biasS[c + 1];
        *(__half2*)(dst + ((g)          * PITCH_H + c) * 2) =
            __floats2half2_rn(fmaxf(accLo[f][0] + b0, 0.f), fmaxf(accLo[f][1] + b1, 0.f));
        *(__half2*)(dst + ((g + 8)      * PITCH_H + c) * 2) =
            __floats2half2_rn(fmaxf(accLo[f][2] + b0, 0.f), fmaxf(accLo[f][3] + b1, 0.f));
        *(__half2*)(dst + ((16 + g)     * PITCH_H + c) * 2) =
            __floats2half2_rn(fmaxf(accHi[f][0] + b0, 0.f), fmaxf(accHi[f][1] + b1, 0.f));
        *(__half2*)(dst + ((16 + g + 8) * PITCH_H + c) * 2) =
            __floats2half2_rn(fmaxf(accHi[f][2] + b0, 0.f), fmaxf(accHi[f][3] + b1, 0.f));
    }
}

// output layer: kstep0 W preloaded; prefetches NEXT TILE's layer1 kstep0.
__device__ __forceinline__ void layer_out(
    uint32_t srcU32, const float* __restrict__ b4S, float* __restrict__ outg,
    int colg, int lane, int g, int tig,
    uint4 w,
    const uint4* __restrict__ imgp,           // kstep1 base, pre-offset
    const uint4* __restrict__ nextp,          // layer1 kstep0, pre-offset
    uint4 (&wout)[4])
{
    const int rlo  = (lane & 7) + ((lane >> 3) & 1) * 8;
    const int colb = (lane >> 4) * 8;
    uint32_t aLoA = srcU32 + (rlo * PITCH_H + colb) * 2;
    uint32_t aHiA = aLoA + 16 * PITCH_H * 2;

    float accLo[2][4], accHi[2][4];
    #pragma unroll
    for (int f = 0; f < 2; f++)
        #pragma unroll
        for (int q = 0; q < 4; q++) { accLo[f][q] = 0.f; accHi[f][q] = 0.f; }

    #pragma unroll
    for (int ks = 0; ks < 32; ks++) {
        uint4 n;
        if (ks + 1 < 32) { n = __ldg(imgp); imgp += 8 * 32; }
        uint32_t aLo[4], aHi[4];
        ldmA(aLo, aLoA); aLoA += 32;
        ldmA(aHi, aHiA); aHiA += 32;
        mma16816(accLo[0], aLo, w.x, w.y);
        mma16816(accLo[1], aLo, w.z, w.w);
        mma16816(accHi[0], aHi, w.x, w.y);
        mma16816(accHi[1], aHi, w.z, w.w);
        if (ks + 1 < 32) w = n;
    }

    // prefetch next tile's layer1 kstep0
    wout[0] = __ldg(nextp);
    wout[1] = __ldg(nextp + 32);
    wout[2] = __ldg(nextp + 64);
    wout[3] = __ldg(nextp + 96);

    #pragma unroll
    for (int f = 0; f < 2; f++) {
        const int n = colg * 16 + f * 8 + tig * 2;
        if (n < KN) {
            const float b0 = b4S[n], b1 = b4S[n + 1];
            *(float2*)(outg + (g)          * KN + n) = make_float2(accLo[f][0] + b0, accLo[f][1] + b1);
            *(float2*)(outg + (g + 8)      * KN + n) = make_float2(accLo[f][2] + b0, accLo[f][3] + b1);
            *(float2*)(outg + (16 + g)     * KN + n) = make_float2(accHi[f][0] + b0, accHi[f][1] + b1);
            *(float2*)(outg + (16 + g + 8) * KN + n) = make_float2(accHi[f][2] + b0, accHi[f][3] + b1);
        }
    }
}

// ---------------------------------------------------------------------------
// stage0a + normalize (unchanged from round 12)
// ---------------------------------------------------------------------------
__device__ __forceinline__ void stage0a_issue(
    int rowbase, char* __restrict__ Fn, uint32_t rawU32,
    const float* __restrict__ x,
    const float* __restrict__ minv, const float* __restrict__ maxv,
    const float* __restrict__ pivots, const float* __restrict__ knnd,
    const float* __restrict__ qmean, const float* __restrict__ qstd,
    int t)
{
    const int row = rowbase + t;
    const float4 xv4 = __ldg((const float4*)x + row);
    float xs[4] = {xv4.x, xv4.y, xv4.z, xv4.w};
    int idx = 0;
    float diag2 = 0.f;
    __half* arow = (__half*)(Fn + t * PITCH_F * 2);
    #pragma unroll
    for (int d = 0; d < DIMN; d++) {
        const float mn = minv[d], mx = maxv[d];
        const float s = (xs[d] - mn) / (mx - mn) * 16.f;
        int bi = (int)floorf(s);
        bi = bi < 0 ? 0 : (bi > 15 ? 15 : bi);
        idx = (idx << 4) + bi;
        const float bw = (mx - mn) * 0.0625f;
        diag2 += bw * bw;
        arow[d] = __float2half((xs[d] - qmean[d]) / qstd[d]);
    }
    float d2 = 0.f;
    #pragma unroll
    for (int d = 0; d < DIMN; d++) {
        const float dd = xs[d] - pivots[idx * DIMN + d];
        d2 += dd * dd;
    }
    arow[DIMN] = __float2half(sqrtf(d2 / diag2));

    const char* src = (const char*)(knnd + (size_t)idx * KN);
    const uint32_t dst = rawU32 + t * 400;
    #pragma unroll
    for (int i = 0; i < 25; i++)
        cpasync16(dst + i * 16, src + i * 16);
    CP_COMMIT();
}

__device__ __forceinline__ void normalize_raw(
    const char* __restrict__ sRaw, char* __restrict__ Fn,
    const float* __restrict__ sKm, const float* __restrict__ sKi, int tid)
{
    for (int i = tid; i < TILE_M * KN; i += THREADS) {
        const int r = i / KN, j = i - r * KN;
        const float v = ((const float*)(sRaw + r * 400))[j];
        ((__half*)(Fn + r * PITCH_F * 2))[DIMN + 1 + j] =
            __float2half((v - sKm[j]) * sKi[j]);
    }
}

// ---------------------------------------------------------------------------
extern "C" __global__ void __launch_bounds__(THREADS, 2)
pivnet_mma(
    const float* __restrict__ x,
    const float* __restrict__ minv,  const float* __restrict__ maxv,
    const float* __restrict__ pivots, const float* __restrict__ knnd,
    const float* __restrict__ qmean, const float* __restrict__ qstd,
    const float* __restrict__ kmean, const float* __restrict__ kstd,
    const float* __restrict__ b1, const float* __restrict__ b2,
    const float* __restrict__ b3, const float* __restrict__ b4,
    float* __restrict__ out)
{
    extern __shared__ char smem[];
    char*  sH0  = smem + SM_H0;
    char*  sH1  = smem + SM_H1;
    char*  sRaw = smem + SM_RAW;
    float* sB1  = (float*)(smem + SM_B1);
    float* sB2  = (float*)(smem + SM_B2);
    float* sB3  = (float*)(smem + SM_B3);
    float* sB4  = (float*)(smem + SM_B4);
    float* sKm  = (float*)(smem + SM_KM);
    float* sKi  = (float*)(smem + SM_KI);

    const int tid  = threadIdx.x;
    const int wid  = tid >> 5;
    const int lane = tid & 31;
    const int g    = lane >> 2;
    const int tig  = lane & 3;
    const int colg = wid;

    const uint32_t h0u  = smem_u32(sH0);
    const uint32_t h1u  = smem_u32(sH1);
    const uint32_t rawU = smem_u32(sRaw);

    char* Fc = smem + SM_F0;
    char* Fn = smem + SM_F1;

    // pre-offset fragment base pointers for this warp/lane
    const uint4* base1 = g_Wfrag + OFF1 + (colg * 4) * 32 + lane;
    const uint4* base2 = g_Wfrag + OFF2 + (colg * 4) * 32 + lane;
    const uint4* base3 = g_Wfrag + OFF3 + (colg * 4) * 32 + lane;
    const uint4* base4 = g_Wfrag + OFF4 + colg * 32 + lane;

    for (int j = tid; j < KN; j += THREADS) {
        sKm[j] = kmean[j];
        sKi[j] = 1.f / kstd[j];
    }
    for (int j = tid; j < 512; j += THREADS) {
        sB1[j] = b1[j];
        sB2[j] = b2[j];
        sB3[j] = b3[j];
        if (j < 128) sB4[j] = (j < KN) ? b4[j] : 0.f;
    }
    for (int j = tid * 16; j < 2 * TILE_M * PITCH_F * 2; j += THREADS * 16)
        *(uint4*)(smem + SM_F0 + j) = make_uint4(0, 0, 0, 0);
    __syncthreads();

    const int tile0 = blockIdx.x;
    uint4 wA[4], wB[4], wC[4], wD[4];
    // prologue: layer1 kstep0 prefetch + first tile stage0
    wA[0] = __ldg(base1);
    wA[1] = __ldg(base1 + 32);
    wA[2] = __ldg(base1 + 64);
    wA[3] = __ldg(base1 + 96);
    if (tile0 < NTILES) {
        if (tid < TILE_M)
            stage0a_issue(tile0 * TILE_M, Fc, rawU, x, minv, maxv, pivots,
                          knnd, qmean, qstd, tid);
        CP_WAIT0();
        __syncthreads();
        normalize_raw(sRaw, Fc, sKm, sKi, tid);
        __syncthreads();
    }

    for (int tile = tile0; tile < NTILES; tile += gridDim.x) {
        const int rowbase = tile * TILE_M;
        const int ntile = tile + gridDim.x;

        layer_relu<7, PITCH_F>(smem_u32(Fc), sH0, sB1, colg, lane, g, tig,
                               wA[0], wA[1], wA[2], wA[3],
                               base1 + 1024, base2, wB);
        __syncthreads();
        layer_relu<32, PITCH_H>(h0u, sH1, sB2, colg, lane, g, tig,
                                wB[0], wB[1], wB[2], wB[3],
                                base2 + 1024, base3, wC);
        __syncthreads();
        layer_relu<32, PITCH_H>(h1u, sH0, sB3, colg, lane, g, tig,
                                wC[0], wC[1], wC[2], wC[3],
                                base3 + 1024, base4, wD);
        __syncthreads();

        if (wid == 0 && ntile < NTILES)
            stage0a_issue(ntile * TILE_M, Fn, rawU, x, minv, maxv, pivots,
                          knnd, qmean, qstd, lane);

        layer_out(h0u, sB4, out + (size_t)rowbase * KN, colg, lane, g, tig,
                  wD[0], base4 + 256, base1, wA);

        CP_WAIT0();
        __syncthreads();
        if (ntile < NTILES)
            normalize_raw(sRaw, Fn, sKm, sKi, tid);
        __syncthreads();

        char* t_ = Fc; Fc = Fn; Fn = t_;
    }
}

// ---------------------------------------------------------------------------
extern "C" void kernel_launch(void* const* d_in, const int* in_sizes, int n_in,
                              void* d_out, int out_size)
{
    const float* x     = (const float*)d_in[0];
    const float* minv  = (const float*)d_in[1];
    const float* maxv  = (const float*)d_in[2];
    const float* piv   = (const float*)d_in[3];
    const float* knnd  = (const float*)d_in[4];
    const float* qmean = (const float*)d_in[5];
    const float* qstd  = (const float*)d_in[6];
    const float* kmean = (const float*)d_in[7];
    const float* kstd  = (const float*)d_in[8];
    const float* W1    = (const float*)d_in[9];
    const float* b1    = (const float*)d_in[10];
    const float* W2    = (const float*)d_in[11];
    const float* b2    = (const float*)d_in[12];
    const float* W3    = (const float*)d_in[13];
    const float* b3    = (const float*)d_in[14];
    const float* W4    = (const float*)d_in[15];
    const float* b4    = (const float*)d_in[16];
    float* out = (float*)d_out;

    pivnet_prepack<<<256, 256>>>(W1, W2, W3, W4);

    cudaFuncSetAttribute(pivnet_mma,
                         cudaFuncAttributeMaxDynamicSharedMemorySize, SMEM_BYTES);
    pivnet_mma<<<GRID_CTAS, THREADS, SMEM_BYTES>>>(
        x, minv, maxv, piv, knnd, qmean, qstd, kmean, kstd,
        b1, b2, b3, b4, out);
}

// round 16
// speedup vs baseline: 10.9545x; 1.0044x over previous
#include <cuda_runtime.h>
#include <cuda_fp16.h>
#include <cstdint>
#include <cstring>

// ===========================================================================
// PivNet — mma.sync (HMMA), fp16 in / fp32 acc.
// Round 15 (= round 14 resubmit; prior bench died to container-acquisition
// infra failure, not a kernel fault — audit in commit message):
//   (a) 2-deep W prefetch in relu mainloops (L2 lat 234-262 cyc > one-kstep
//       ~200 cyc, so 1-deep was short),
//   (b) 4-deep W queue in layer_out fed by layer3's boundary prefetch,
//   (c) stage0 distributed across all 8 warps with per-warp normalize
//       (kills warp0 serialization + 2 barriers).
// ===========================================================================

#define B_TOTAL   524288
#define DIMN      4
#define KN        100
#define TILE_M    32
#define THREADS   256
#define NTILES    (B_TOTAL / TILE_M)   // 16384
#define GRID_CTAS 304
#define PITCH_H   520                  // halfs
#define PITCH_F   120                  // halfs

// fragment image offsets (uint4 units) — layout verified rounds 5-13
#define OFF1 0
#define OFF2 7168
#define OFF3 39936
#define OFF4 72704
#define IMG_U4 80896

__device__ __align__(16) uint4 g_Wfrag[IMG_U4];

// smem layout (bytes)
#define SM_H0    0
#define SM_H1    33280
#define SM_F0    66560
#define SM_F1    74240
#define SM_RAW   81920
#define SM_B1    94720
#define SM_B2    96768
#define SM_B3    98816
#define SM_B4    100864
#define SM_KM    101376
#define SM_KI    101776
#define SM_IDX   102176
#define SMEM_BYTES 102400

// ---------------------------------------------------------------------------
__device__ __forceinline__ uint32_t smem_u32(const void* p) {
    uint32_t a;
    asm("{ .reg .u64 t; cvta.to.shared.u64 t, %1; cvt.u32.u64 %0, t; }"
        : "=r"(a) : "l"(p));
    return a;
}
__device__ __forceinline__ void ldmA(uint32_t a[4], uint32_t addr) {
    asm volatile("ldmatrix.sync.aligned.m8n8.x4.shared.b16 {%0,%1,%2,%3}, [%4];"
                 : "=r"(a[0]), "=r"(a[1]), "=r"(a[2]), "=r"(a[3]) : "r"(addr));
}
__device__ __forceinline__ void mma16816(float c[4], const uint32_t a[4],
                                         uint32_t b0, uint32_t b1) {
    asm volatile("mma.sync.aligned.m16n8k16.row.col.f32.f16.f16.f32 "
                 "{%0,%1,%2,%3}, {%4,%5,%6,%7}, {%8,%9}, {%0,%1,%2,%3};"
                 : "+f"(c[0]), "+f"(c[1]), "+f"(c[2]), "+f"(c[3])
                 : "r"(a[0]), "r"(a[1]), "r"(a[2]), "r"(a[3]), "r"(b0), "r"(b1));
}
__device__ __forceinline__ uint32_t packh2(float lo, float hi) {
    __half2 h = __floats2half2_rn(lo, hi);
    uint32_t u; memcpy(&u, &h, 4); return u;
}
__device__ __forceinline__ void cpasync16(uint32_t saddr, const void* g) {
    asm volatile("cp.async.cg.shared.global [%0], [%1], 16;"
                 :: "r"(saddr), "l"(g) : "memory");
}
#define CP_COMMIT() asm volatile("cp.async.commit_group;" ::: "memory")
#define CP_WAIT0()  asm volatile("cp.async.wait_group 0;" ::: "memory")

// ---------------------------------------------------------------------------
// prepack (unchanged, layout verified)
// ---------------------------------------------------------------------------
extern "C" __global__ void pivnet_prepack(
    const float* __restrict__ W1, const float* __restrict__ W2,
    const float* __restrict__ W3, const float* __restrict__ W4)
{
    for (int u = blockIdx.x * blockDim.x + threadIdx.x; u < IMG_U4;
         u += gridDim.x * blockDim.x) {
        const float* W; int Ksrc, Nsrc, stride, npairs, lu;
        if (u < OFF2)      { W = W1; Ksrc = 105; Nsrc = 512; stride = 512; npairs = 32; lu = u - OFF1; }
        else if (u < OFF3) { W = W2; Ksrc = 512; Nsrc = 512; stride = 512; npairs = 32; lu = u - OFF2; }
        else if (u < OFF4) { W = W3; Ksrc = 512; Nsrc = 512; stride = 512; npairs = 32; lu = u - OFF3; }
        else               { W = W4; Ksrc = 512; Nsrc = 100; stride = 100; npairs = 8;  lu = u - OFF4; }
        const int PB = npairs * 32;
        const int kblk = lu / PB, rem = lu - kblk * PB;
        const int npair = rem >> 5, lane = rem & 31;
        const int g = lane >> 2, tig = lane & 3;
        const int k0 = kblk * 16 + tig * 2;
        const int na = npair * 16 + g, nb = na + 8;
        auto rd = [&](int k, int n) -> float {
            return (k < Ksrc && n < Nsrc) ? W[k * stride + n] : 0.f;
        };
        uint4 v;
        v.x = packh2(rd(k0,     na), rd(k0 + 1, na));
        v.y = packh2(rd(k0 + 8, na), rd(k0 + 9, na));
        v.z = packh2(rd(k0,     nb), rd(k0 + 1, nb));
        v.w = packh2(rd(k0 + 8, nb), rd(k0 + 9, nb));
        g_Wfrag[u] = v;
    }
}

// ---------------------------------------------------------------------------
// relu layer, 2-deep W pipeline. kstep0 passed in (win); kstep1 loaded at
// entry; loop prefetches ks+2. Ends by prefetching next layer's kstep0 set.
// ---------------------------------------------------------------------------
template<int KSTEPS, int PITCH>
__device__ __forceinline__ void layer_relu(
    uint32_t srcU32, char* __restrict__ dst, const float* __restrict__ biasS,
    int colg, int lane, int g, int tig,
    const uint4 win[4],
    const uint4* __restrict__ imgp,           // kstep1 base, pre-offset
    const uint4* __restrict__ nextp, int nstride,
    uint4 (&wout)[4])
{
    const int rlo  = (lane & 7) + ((lane >> 3) & 1) * 8;
    const int colb = (lane >> 4) * 8;
    uint32_t aLoA = srcU32 + (rlo * PITCH + colb) * 2;
    uint32_t aHiA = aLoA + 16 * PITCH * 2;

    float accLo[8][4], accHi[8][4];
    #pragma unroll
    for (int f = 0; f < 8; f++)
        #pragma unroll
        for (int q = 0; q < 4; q++) { accLo[f][q] = 0.f; accHi[f][q] = 0.f; }

    uint4 c0 = win[0], c1 = win[1], c2 = win[2], c3 = win[3];
    uint4 n0, n1, n2, n3;
    if (KSTEPS > 1) {
        n0 = __ldg(imgp);
        n1 = __ldg(imgp + 32);
        n2 = __ldg(imgp + 64);
        n3 = __ldg(imgp + 96);
    }
    const uint4* p2 = imgp + 1024;            // kstep2

    #pragma unroll
    for (int ks = 0; ks < KSTEPS; ks++) {
        uint4 f0, f1, f2, f3;
        if (ks + 2 < KSTEPS) {
            f0 = __ldg(p2);
            f1 = __ldg(p2 + 32);
            f2 = __ldg(p2 + 64);
            f3 = __ldg(p2 + 96);
            p2 += 1024;
        }
        uint32_t aLo[4], aHi[4];
        ldmA(aLo, aLoA); aLoA += 32;
        ldmA(aHi, aHiA); aHiA += 32;
        mma16816(accLo[0], aLo, c0.x, c0.y);
        mma16816(accLo[1], aLo, c0.z, c0.w);
        mma16816(accHi[0], aHi, c0.x, c0.y);
        mma16816(accHi[1], aHi, c0.z, c0.w);
        mma16816(accLo[2], aLo, c1.x, c1.y);
        mma16816(accLo[3], aLo, c1.z, c1.w);
        mma16816(accHi[2], aHi, c1.x, c1.y);
        mma16816(accHi[3], aHi, c1.z, c1.w);
        mma16816(accLo[4], aLo, c2.x, c2.y);
        mma16816(accLo[5], aLo, c2.z, c2.w);
        mma16816(accHi[4], aHi, c2.x, c2.y);
        mma16816(accHi[5], aHi, c2.z, c2.w);
        mma16816(accLo[6], aLo, c3.x, c3.y);
        mma16816(accLo[7], aLo, c3.z, c3.w);
        mma16816(accHi[6], aHi, c3.x, c3.y);
        mma16816(accHi[7], aHi, c3.z, c3.w);
        if (ks + 1 < KSTEPS) { c0 = n0; c1 = n1; c2 = n2; c3 = n3; }
        if (ks + 2 < KSTEPS) { n0 = f0; n1 = f1; n2 = f2; n3 = f3; }
    }

    // boundary prefetch: next layer's kstep0 set (stride selects image shape)
    wout[0] = __ldg(nextp);
    wout[1] = __ldg(nextp + nstride);
    wout[2] = __ldg(nextp + 2 * nstride);
    wout[3] = __ldg(nextp + 3 * nstride);

    #pragma unroll
    for (int f = 0; f < 8; f++) {
        const int c = colg * 64 + f * 8 + tig * 2;
        const float b0 = biasS[c], b1 = biasS[c + 1];
        *(__half2*)(dst + ((g)          * PITCH_H + c) * 2) =
            __floats2half2_rn(fmaxf(accLo[f][0] + b0, 0.f), fmaxf(accLo[f][1] + b1, 0.f));
        *(__half2*)(dst + ((g + 8)      * PITCH_H + c) * 2) =
            __floats2half2_rn(fmaxf(accLo[f][2] + b0, 0.f), fmaxf(accLo[f][3] + b1, 0.f));
        *(__half2*)(dst + ((16 + g)     * PITCH_H + c) * 2) =
            __floats2half2_rn(fmaxf(accHi[f][0] + b0, 0.f), fmaxf(accHi[f][1] + b1, 0.f));
        *(__half2*)(dst + ((16 + g + 8) * PITCH_H + c) * 2) =
            __floats2half2_rn(fmaxf(accHi[f][2] + b0, 0.f), fmaxf(accHi[f][3] + b1, 0.f));
    }
}

// output layer: 4-deep W queue (wq = ksteps 0..3 preloaded by layer3's
// boundary prefetch); mainloop prefetches at distance 4. Ends by prefetching
// next tile's layer1 kstep0 set.
__device__ __forceinline__ void layer_out(
    uint32_t srcU32, const float* __restrict__ b4S, float* __restrict__ outg,
    int colg, int lane, int g, int tig,
    const uint4 wqin[4],
    const uint4* __restrict__ imgp,           // kstep4 base, pre-offset
    const uint4* __restrict__ nextp,
    uint4 (&wout)[4])
{
    const int rlo  = (lane & 7) + ((lane >> 3) & 1) * 8;
    const int colb = (lane >> 4) * 8;
    uint32_t aLoA = srcU32 + (rlo * PITCH_H + colb) * 2;
    uint32_t aHiA = aLoA + 16 * PITCH_H * 2;

    float accLo[2][4], accHi[2][4];
    #pragma unroll
    for (int f = 0; f < 2; f++)
        #pragma unroll
        for (int q = 0; q < 4; q++) { accLo[f][q] = 0.f; accHi[f][q] = 0.f; }

    uint4 q0 = wqin[0], q1 = wqin[1], q2 = wqin[2], q3 = wqin[3];

    #pragma unroll
    for (int ks = 0; ks < 32; ks++) {
        uint4 n;
        if (ks + 4 < 32) { n = __ldg(imgp); imgp += 256; }
        uint32_t aLo[4], aHi[4];
        ldmA(aLo, aLoA); aLoA += 32;
        ldmA(aHi, aHiA); aHiA += 32;
        mma16816(accLo[0], aLo, q0.x, q0.y);
        mma16816(accLo[1], aLo, q0.z, q0.w);
        mma16816(accHi[0], aHi, q0.x, q0.y);
        mma16816(accHi[1], aHi, q0.z, q0.w);
        q0 = q1; q1 = q2; q2 = q3;
        if (ks + 4 < 32) q3 = n;
    }

    wout[0] = __ldg(nextp);
    wout[1] = __ldg(nextp + 32);
    wout[2] = __ldg(nextp + 64);
    wout[3] = __ldg(nextp + 96);

    #pragma unroll
    for (int f = 0; f < 2; f++) {
        const int n = colg * 16 + f * 8 + tig * 2;
        if (n < KN) {
            const float b0 = b4S[n], b1 = b4S[n + 1];
            *(float2*)(outg + (g)          * KN + n) = make_float2(accLo[f][0] + b0, accLo[f][1] + b1);
            *(float2*)(outg + (g + 8)      * KN + n) = make_float2(accLo[f][2] + b0, accLo[f][3] + b1);
            *(float2*)(outg + (16 + g)     * KN + n) = make_float2(accHi[f][0] + b0, accHi[f][1] + b1);
            *(float2*)(outg + (16 + g + 8) * KN + n) = make_float2(accHi[f][2] + b0, accHi[f][3] + b1);
        }
    }
}

// ---------------------------------------------------------------------------
// stage0 distributed: each warp owns 4 rows. Lanes 0..3 do hash/qn/dist,
// then all 32 lanes cp.async the 4 raw knnd rows (100 x 16B chunks).
// ---------------------------------------------------------------------------
__device__ __forceinline__ void stage0a_dist(
    int rowbase, char* __restrict__ Fn, uint32_t rawU32,
    const float* __restrict__ x,
    const float* __restrict__ minv, const float* __restrict__ maxv,
    const float* __restrict__ pivots, const float* __restrict__ knnd,
    const float* __restrict__ qmean, const float* __restrict__ qstd,
    int* __restrict__ sIdx, int wid, int lane)
{
    const int r = wid * 4 + lane;
    if (lane < 4) {
        const int row = rowbase + r;
        const float4 xv4 = __ldg((const float4*)x + row);
        float xs[4] = {xv4.x, xv4.y, xv4.z, xv4.w};
        int idx = 0;
        float diag2 = 0.f;
        __half* arow = (__half*)(Fn + r * PITCH_F * 2);
        #pragma unroll
        for (int d = 0; d < DIMN; d++) {
            const float mn = minv[d], mx = maxv[d];
            const float s = (xs[d] - mn) / (mx - mn) * 16.f;
            int bi = (int)floorf(s);
            bi = bi < 0 ? 0 : (bi > 15 ? 15 : bi);
            idx = (idx << 4) + bi;
            const float bw = (mx - mn) * 0.0625f;
            diag2 += bw * bw;
            arow[d] = __float2half((xs[d] - qmean[d]) / qstd[d]);
        }
        sIdx[r] = idx;
        float d2 = 0.f;
        #pragma unroll
        for (int d = 0; d < DIMN; d++) {
            const float dd = xs[d] - pivots[idx * DIMN + d];
            d2 += dd * dd;
        }
        arow[DIMN] = __float2half(sqrtf(d2 / diag2));
    }
    __syncwarp();
    #pragma unroll
    for (int j = lane; j < 100; j += 32) {
        const int rr = j / 25, i = j - rr * 25;
        const int row = wid * 4 + rr;
        const char* src = (const char*)(knnd + (size_t)sIdx[row] * KN) + i * 16;
        cpasync16(rawU32 + row * 400 + i * 16, src);
    }
    CP_COMMIT();
}

// per-warp normalize of own 4 rows
__device__ __forceinline__ void normalize_own(
    const char* __restrict__ sRaw, char* __restrict__ Fn,
    const float* __restrict__ sKm, const float* __restrict__ sKi,
    int wid, int lane)
{
    #pragma unroll
    for (int j = lane; j < 400; j += 32) {
        const int rr = j / 100, jj = j - rr * 100;
        const int row = wid * 4 + rr;
        const float v = ((const float*)(sRaw + row * 400))[jj];
        ((__half*)(Fn + row * PITCH_F * 2))[DIMN + 1 + jj] =
            __float2half((v - sKm[jj]) * sKi[jj]);
    }
}

// ---------------------------------------------------------------------------
extern "C" __global__ void __launch_bounds__(THREADS, 2)
pivnet_mma(
    const float* __restrict__ x,
    const float* __restrict__ minv,  const float* __restrict__ maxv,
    const float* __restrict__ pivots, const float* __restrict__ knnd,
    const float* __restrict__ qmean, const float* __restrict__ qstd,
    const float* __restrict__ kmean, const float* __restrict__ kstd,
    const float* __restrict__ b1, const float* __restrict__ b2,
    const float* __restrict__ b3, const float* __restrict__ b4,
    float* __restrict__ out)
{
    extern __shared__ char smem[];
    char*  sH0  = smem + SM_H0;
    char*  sH1  = smem + SM_H1;
    char*  sRaw = smem + SM_RAW;
    float* sB1  = (float*)(smem + SM_B1);
    float* sB2  = (float*)(smem + SM_B2);
    float* sB3  = (float*)(smem + SM_B3);
    float* sB4  = (float*)(smem + SM_B4);
    float* sKm  = (float*)(smem + SM_KM);
    float* sKi  = (float*)(smem + SM_KI);
    int*   sIdx = (int*)(smem + SM_IDX);

    const int tid  = threadIdx.x;
    const int wid  = tid >> 5;
    const int lane = tid & 31;
    const int g    = lane >> 2;
    const int tig  = lane & 3;
    const int colg = wid;

    const uint32_t h0u  = smem_u32(sH0);
    const uint32_t h1u  = smem_u32(sH1);
    const uint32_t rawU = smem_u32(sRaw);
    uint32_t fcU = smem_u32(smem + SM_F0);
    uint32_t fnU = smem_u32(smem + SM_F1);
    char* Fc = smem + SM_F0;
    char* Fn = smem + SM_F1;

    const uint4* base1 = g_Wfrag + OFF1 + (colg * 4) * 32 + lane;
    const uint4* base2 = g_Wfrag + OFF2 + (colg * 4) * 32 + lane;
    const uint4* base3 = g_Wfrag + OFF3 + (colg * 4) * 32 + lane;
    const uint4* base4 = g_Wfrag + OFF4 + colg * 32 + lane;

    for (int j = tid; j < KN; j += THREADS) {
        sKm[j] = kmean[j];
        sKi[j] = 1.f / kstd[j];
    }
    for (int j = tid; j < 512; j += THREADS) {
        sB1[j] = b1[j];
        sB2[j] = b2[j];
        sB3[j] = b3[j];
        if (j < 128) sB4[j] = (j < KN) ? b4[j] : 0.f;
    }
    for (int j = tid * 16; j < 2 * TILE_M * PITCH_F * 2; j += THREADS * 16)
        *(uint4*)(smem + SM_F0 + j) = make_uint4(0, 0, 0, 0);
    __syncthreads();

    const int tile0 = blockIdx.x;
    uint4 wA[4], wB[4], wC[4], wD[4];
    wA[0] = __ldg(base1);
    wA[1] = __ldg(base1 + 32);
    wA[2] = __ldg(base1 + 64);
    wA[3] = __ldg(base1 + 96);

    if (tile0 < NTILES) {
        stage0a_dist(tile0 * TILE_M, Fc, rawU, x, minv, maxv, pivots,
                     knnd, qmean, qstd, sIdx, wid, lane);
        CP_WAIT0();
        __syncwarp();
        normalize_own(sRaw, Fc, sKm, sKi, wid, lane);
        __syncthreads();
    }

    for (int tile = tile0; tile < NTILES; tile += gridDim.x) {
        const int rowbase = tile * TILE_M;
        const int ntile = tile + gridDim.x;

        layer_relu<7, PITCH_F>(fcU, sH0, sB1, colg, lane, g, tig,
                               wA, base1 + 1024, base2, 32, wB);
        __syncthreads();
        layer_relu<32, PITCH_H>(h0u, sH1, sB2, colg, lane, g, tig,
                                wB, base2 + 1024, base3, 32, wC);
        __syncthreads();
        layer_relu<32, PITCH_H>(h1u, sH0, sB3, colg, lane, g, tig,
                                wC, base3 + 1024, base4, 256, wD);
        __syncthreads();

        if (ntile < NTILES)
            stage0a_dist(ntile * TILE_M, Fn, rawU, x, minv, maxv, pivots,
                         knnd, qmean, qstd, sIdx, wid, lane);

        layer_out(h0u, sB4, out + (size_t)rowbase * KN, colg, lane, g, tig,
                  wD, base4 + 1024, base1, wA);

        CP_WAIT0();
        __syncwarp();
        if (ntile < NTILES)
            normalize_own(sRaw, Fn, sKm, sKi, wid, lane);
        __syncthreads();

        char* t_ = Fc; Fc = Fn; Fn = t_;
        uint32_t tu = fcU; fcU = fnU; fnU = tu;
    }
}

// ---------------------------------------------------------------------------
extern "C" void kernel_launch(void* const* d_in, const int* in_sizes, int n_in,
                              void* d_out, int out_size)
{
    const float* x     = (const float*)d_in[0];
    const float* minv  = (const float*)d_in[1];
    const float* maxv  = (const float*)d_in[2];
    const float* piv   = (const float*)d_in[3];
    const float* knnd  = (const float*)d_in[4];
    const float* qmean = (const float*)d_in[5];
    const float* qstd  = (const float*)d_in[6];
    const float* kmean = (const float*)d_in[7];
    const float* kstd  = (const float*)d_in[8];
    const float* W1    = (const float*)d_in[9];
    const float* b1    = (const float*)d_in[10];
    const float* W2    = (const float*)d_in[11];
    const float* b2    = (const float*)d_in[12];
    const float* W3    = (const float*)d_in[13];
    const float* b3    = (const float*)d_in[14];
    const float* W4    = (const float*)d_in[15];
    const float* b4    = (const float*)d_in[16];
    float* out = (float*)d_out;

    pivnet_prepack<<<256, 256>>>(W1, W2, W3, W4);

    cudaFuncSetAttribute(pivnet_mma,
                         cudaFuncAttributeMaxDynamicSharedMemorySize, SMEM_BYTES);
    pivnet_mma<<<GRID_CTAS, THREADS, SMEM_BYTES>>>(
        x, minv, maxv, piv, knnd, qmean, qstd, kmean, kstd,
        b1, b2, b3, b4, out);
}